// round 1
// baseline (speedup 1.0000x reference)
#include <cuda_runtime.h>
#include <cuda_bf16.h>
#include <math.h>

#define B_ 4
#define T_ 512
#define D_ 768
#define H_ 12
#define HD_ 64
#define L_ 12
#define DFF_ 2048
#define VOCAB_ 50257
#define NMEM_ 1024
#define TOPK_ 8
#define NLAT_ 4
#define CAP_ 64
#define BT_ (B_*T_)
#define QKVD_ (3*D_)

// ------------------- scratch (device globals; no allocation) -------------------
__device__ float g_X[BT_*D_];
__device__ float g_Y[BT_*D_];
__device__ float g_Hb[BT_*D_];
__device__ float g_QKV[BT_*QKVD_];
__device__ float g_P[(size_t)B_*H_*T_*T_];
__device__ float g_ATT[BT_*D_];
__device__ float g_U[BT_*DFF_];
__device__ float g_V2[BT_*DFF_];
__device__ float g_SIM[BT_*NMEM_];
__device__ float g_RETP[BT_*D_];
__device__ float g_RET[BT_*D_];
__device__ float g_GI[BT_*2*D_];
__device__ float g_H1[BT_*(D_/2)];
__device__ float g_SC[BT_];
__device__ int   g_SEL[BT_];

// ------------------- SGEMM: C[M,N] = A[M,K] @ B[N,K]^T (+C) -------------------
template<bool ACC, bool NGUARD>
__global__ __launch_bounds__(256) void sgemm_nt(const float* __restrict__ A,
                                                const float* __restrict__ Bw,
                                                float* __restrict__ C,
                                                int M, int N, int K) {
    const int BM = 128, BN = 128, BK = 16;
    __shared__ float As[BK][BM];
    __shared__ float Bs[BK][BN];
    int bm = blockIdx.y * BM, bn = blockIdx.x * BN;
    int tid = threadIdx.x;
    int tx = tid & 15, ty = tid >> 4;
    float acc[8][8];
#pragma unroll
    for (int i = 0; i < 8; i++)
#pragma unroll
        for (int j = 0; j < 8; j++) acc[i][j] = 0.f;

    for (int k0 = 0; k0 < K; k0 += BK) {
#pragma unroll
        for (int it = 0; it < 2; it++) {
            int idx = tid + it * 256;
            int r = idx >> 2;
            int kq = (idx & 3) * 4;
            float4 a = *(const float4*)(A + (size_t)(bm + r) * K + k0 + kq);
            As[kq + 0][r] = a.x; As[kq + 1][r] = a.y;
            As[kq + 2][r] = a.z; As[kq + 3][r] = a.w;
            float4 b;
            if (!NGUARD || (bn + r) < N)
                b = *(const float4*)(Bw + (size_t)(bn + r) * K + k0 + kq);
            else
                b = make_float4(0.f, 0.f, 0.f, 0.f);
            Bs[kq + 0][r] = b.x; Bs[kq + 1][r] = b.y;
            Bs[kq + 2][r] = b.z; Bs[kq + 3][r] = b.w;
        }
        __syncthreads();
#pragma unroll
        for (int kk = 0; kk < BK; kk++) {
            float ar[8], br[8];
#pragma unroll
            for (int i = 0; i < 8; i++) ar[i] = As[kk][ty * 8 + i];
#pragma unroll
            for (int j = 0; j < 8; j++) br[j] = Bs[kk][tx * 8 + j];
#pragma unroll
            for (int i = 0; i < 8; i++)
#pragma unroll
                for (int j = 0; j < 8; j++) acc[i][j] += ar[i] * br[j];
        }
        __syncthreads();
    }
#pragma unroll
    for (int i = 0; i < 8; i++) {
        int row = bm + ty * 8 + i;
#pragma unroll
        for (int j = 0; j < 8; j++) {
            int col = bn + tx * 8 + j;
            if (!NGUARD || col < N) {
                size_t off = (size_t)row * N + col;
                if (ACC) C[off] += acc[i][j];
                else     C[off] = acc[i][j];
            }
        }
    }
}

// ------------------- elementwise / small kernels -------------------
__global__ void embed_k(const int* __restrict__ ids, const float* __restrict__ E,
                        const float* __restrict__ Pw, float* __restrict__ X) {
    int m = blockIdx.x;
    int t = m % T_;
    int id = ids[m];
    for (int i = threadIdx.x; i < D_; i += 256)
        X[(size_t)m * D_ + i] = E[(size_t)id * D_ + i] + Pw[(size_t)t * D_ + i];
}

__global__ void rmsnorm_k(const float* __restrict__ X, const float* __restrict__ w,
                          float* __restrict__ Yb) {
    int m = blockIdx.x;
    const float* x = X + (size_t)m * D_;
    float s = 0.f;
    for (int i = threadIdx.x; i < D_; i += 256) { float v = x[i]; s += v * v; }
    __shared__ float red[256];
    red[threadIdx.x] = s; __syncthreads();
    for (int st = 128; st > 0; st >>= 1) {
        if (threadIdx.x < st) red[threadIdx.x] += red[threadIdx.x + st];
        __syncthreads();
    }
    float scale = rsqrtf(red[0] / (float)D_ + 1e-6f);
    for (int i = threadIdx.x; i < D_; i += 256)
        Yb[(size_t)m * D_ + i] = x[i] * scale * w[i];
}

__global__ void attn_softmax_k(const float* __restrict__ QKV, float* __restrict__ P) {
    int qi = blockIdx.x;
    int bh = blockIdx.y;
    int b = bh / H_, h = bh % H_;
    int tid = threadIdx.x;  // 128
    __shared__ float qs[HD_];
    __shared__ float red[128];
    const float* qrow = QKV + (size_t)(b * T_ + qi) * QKVD_ + h * HD_;
    if (tid < HD_) qs[tid] = qrow[tid];
    __syncthreads();
    int nk = qi + 1;
    float s_local[4];
    float mx = -1e30f;
    int c = 0;
    for (int k = tid; k < nk; k += 128, c++) {
        const float* krow = QKV + (size_t)(b * T_ + k) * QKVD_ + D_ + h * HD_;
        float d = 0.f;
#pragma unroll
        for (int e = 0; e < HD_; e++) d += qs[e] * krow[e];
        d *= 0.125f;
        s_local[c] = d;
        mx = fmaxf(mx, d);
    }
    red[tid] = mx; __syncthreads();
    for (int st = 64; st > 0; st >>= 1) {
        if (tid < st) red[tid] = fmaxf(red[tid], red[tid + st]);
        __syncthreads();
    }
    mx = red[0]; __syncthreads();
    float sum = 0.f;
    c = 0;
    for (int k = tid; k < nk; k += 128, c++) {
        s_local[c] = expf(s_local[c] - mx);
        sum += s_local[c];
    }
    red[tid] = sum; __syncthreads();
    for (int st = 64; st > 0; st >>= 1) {
        if (tid < st) red[tid] += red[tid + st];
        __syncthreads();
    }
    float inv = 1.f / red[0];
    float* prow = P + ((size_t)bh * T_ + qi) * T_;
    c = 0;
    for (int k = tid; k < nk; k += 128, c++) prow[k] = s_local[c] * inv;
}

__global__ void attn_av_k(const float* __restrict__ P, const float* __restrict__ QKV,
                          float* __restrict__ O) {
    int qi = blockIdx.x;
    int bh = blockIdx.y;
    int b = bh / H_, h = bh % H_;
    int tid = threadIdx.x;  // 256
    int d = tid & 63, part = tid >> 6;
    const float* prow = P + ((size_t)bh * T_ + qi) * T_;
    float acc = 0.f;
    int nk = qi + 1;
    for (int k = part; k < nk; k += 4) {
        const float* vrow = QKV + (size_t)(b * T_ + k) * QKVD_ + 2 * D_ + h * HD_;
        acc += prow[k] * vrow[d];
    }
    __shared__ float sh[256];
    sh[tid] = acc; __syncthreads();
    if (part == 0) {
        float r = sh[d] + sh[d + 64] + sh[d + 128] + sh[d + 192];
        O[(size_t)(b * T_ + qi) * D_ + h * HD_ + d] = r;
    }
}

__global__ void swiglu_k(float* __restrict__ U, const float* __restrict__ V, int n) {
    int i = blockIdx.x * blockDim.x + threadIdx.x;
    if (i < n) {
        float u = U[i];
        float s = u / (1.f + expf(-u));
        U[i] = s * V[i];
    }
}

__global__ void router_score_k(const float* __restrict__ X, const float* __restrict__ rw,
                               float* __restrict__ sc) {
    int m = blockIdx.x;
    float s = 0.f;
    for (int i = threadIdx.x; i < D_; i += 256) s += X[(size_t)m * D_ + i] * rw[i];
    __shared__ float red[256];
    red[threadIdx.x] = s; __syncthreads();
    for (int st = 128; st > 0; st >>= 1) {
        if (threadIdx.x < st) red[threadIdx.x] += red[threadIdx.x + st];
        __syncthreads();
    }
    if (threadIdx.x == 0) sc[m] = red[0];
}

__global__ void topk_sel_k(const float* __restrict__ sc, int* __restrict__ sel) {
    int b = blockIdx.x, t = threadIdx.x;  // 512 threads
    __shared__ float s[T_];
    s[t] = sc[b * T_ + t];
    __syncthreads();
    float mine = s[t];
    int rank = 0;
    for (int j = 0; j < T_; j++) {
        float v = s[j];
        if (v > mine || (v == mine && j < t)) rank++;
    }
    sel[b * T_ + t] = (rank < CAP_) ? 1 : 0;
}

__global__ void sel_merge_k(float* __restrict__ X, const float* __restrict__ Y,
                            const int* __restrict__ sel) {
    int m = blockIdx.x;
    if (sel[m]) {
        for (int i = threadIdx.x; i < D_; i += 256)
            X[(size_t)m * D_ + i] = Y[(size_t)m * D_ + i];
    }
}

__global__ void memtopk_k(const float* __restrict__ SIM, const float* __restrict__ MV,
                          float* __restrict__ RETP) {
    int m = blockIdx.x;
    int tid = threadIdx.x;  // 256
    __shared__ float s[NMEM_];
    __shared__ float wts[TOPK_];
    __shared__ int idxs[TOPK_];
    __shared__ float rv[256];
    __shared__ int ri[256];
    const float invs = 0.03608439182435161f;  // 1/sqrt(768)
    for (int i = tid; i < NMEM_; i += 256) s[i] = SIM[(size_t)m * NMEM_ + i] * invs;
    __syncthreads();
    for (int j = 0; j < TOPK_; j++) {
        float bv = -1e30f; int bi = 0x7fffffff;
        for (int i = tid; i < NMEM_; i += 256) {
            if (s[i] > bv) { bv = s[i]; bi = i; }
        }
        rv[tid] = bv; ri[tid] = bi; __syncthreads();
        for (int st = 128; st > 0; st >>= 1) {
            if (tid < st) {
                if (rv[tid + st] > rv[tid] ||
                    (rv[tid + st] == rv[tid] && ri[tid + st] < ri[tid])) {
                    rv[tid] = rv[tid + st]; ri[tid] = ri[tid + st];
                }
            }
            __syncthreads();
        }
        if (tid == 0) { wts[j] = rv[0]; idxs[j] = ri[0]; s[ri[0]] = -1e30f; }
        __syncthreads();
    }
    if (tid == 0) {
        float mx = wts[0];
        float sum = 0.f;
        for (int j = 0; j < TOPK_; j++) { wts[j] = expf(wts[j] - mx); sum += wts[j]; }
        float inv = 1.f / sum;
        for (int j = 0; j < TOPK_; j++) wts[j] *= inv;
    }
    __syncthreads();
    for (int i = tid; i < D_; i += 256) {
        float a = 0.f;
#pragma unroll
        for (int j = 0; j < TOPK_; j++) a += wts[j] * MV[(size_t)idxs[j] * D_ + i];
        RETP[(size_t)m * D_ + i] = a;
    }
}

__global__ void concat_k(const float* __restrict__ X, const float* __restrict__ RET,
                         float* __restrict__ GI) {
    int m = blockIdx.x;
    for (int i = threadIdx.x; i < D_; i += 256) {
        GI[(size_t)m * 2 * D_ + i] = X[(size_t)m * D_ + i];
        GI[(size_t)m * 2 * D_ + D_ + i] = RET[(size_t)m * D_ + i];
    }
}

__global__ void gelu_bias_k(float* __restrict__ H1, const float* __restrict__ b1, int n) {
    int i = blockIdx.x * blockDim.x + threadIdx.x;
    if (i < n) {
        int col = i % (D_ / 2);
        float v = H1[i] + b1[col];
        H1[i] = 0.5f * v * (1.f + erff(v * 0.70710678118654752f));
    }
}

__global__ void gate_k(const float* __restrict__ H1, const float* __restrict__ w2,
                       const float* __restrict__ b2, const float* __restrict__ RET,
                       float* __restrict__ X) {
    int m = blockIdx.x;
    float s = 0.f;
    for (int i = threadIdx.x; i < D_ / 2; i += 256)
        s += H1[(size_t)m * (D_ / 2) + i] * w2[i];
    __shared__ float red[256];
    red[threadIdx.x] = s; __syncthreads();
    for (int st = 128; st > 0; st >>= 1) {
        if (threadIdx.x < st) red[threadIdx.x] += red[threadIdx.x + st];
        __syncthreads();
    }
    __shared__ float gsh;
    if (threadIdx.x == 0) gsh = 1.f / (1.f + expf(-(red[0] + b2[0])));
    __syncthreads();
    float g = gsh;
    for (int i = threadIdx.x; i < D_; i += 256)
        X[(size_t)m * D_ + i] += g * RET[(size_t)m * D_ + i];
}

// ------------------- host orchestration -------------------
static void gemm(const float* A, const float* Bw, float* C, int M, int N, int K, bool acc) {
    dim3 grid((N + 127) / 128, M / 128);
    if (N % 128 == 0) {
        if (acc) sgemm_nt<true, false><<<grid, 256>>>(A, Bw, C, M, N, K);
        else     sgemm_nt<false, false><<<grid, 256>>>(A, Bw, C, M, N, K);
    } else {
        if (acc) sgemm_nt<true, true><<<grid, 256>>>(A, Bw, C, M, N, K);
        else     sgemm_nt<false, true><<<grid, 256>>>(A, Bw, C, M, N, K);
    }
}

struct Ptrs {
    float *X, *Y, *Hb, *QKV, *P, *ATT, *U, *V2, *SIM, *RETP, *RET, *GI, *H1, *SC;
    int* SEL;
};

static void tblock_run(const Ptrs& p, const float* qkv_w, const float* out_w,
                       const float* n1, const float* n2, const float* w1,
                       const float* w2, const float* w3, float* x) {
    rmsnorm_k<<<BT_, 256>>>(x, n1, p.Hb);
    gemm(p.Hb, qkv_w, p.QKV, BT_, QKVD_, D_, false);
    attn_softmax_k<<<dim3(T_, B_ * H_), 128>>>(p.QKV, p.P);
    attn_av_k<<<dim3(T_, B_ * H_), 256>>>(p.P, p.QKV, p.ATT);
    gemm(p.ATT, out_w, x, BT_, D_, D_, true);
    rmsnorm_k<<<BT_, 256>>>(x, n2, p.Hb);
    gemm(p.Hb, w1, p.U, BT_, DFF_, D_, false);
    gemm(p.Hb, w2, p.V2, BT_, DFF_, D_, false);
    swiglu_k<<<(BT_ * DFF_ + 255) / 256, 256>>>(p.U, p.V2, BT_ * DFF_);
    gemm(p.U, w3, x, BT_, D_, DFF_, true);
}

extern "C" void kernel_launch(void* const* d_in, const int* in_sizes, int n_in,
                              void* d_out, int out_size) {
    const int*   ids       = (const int*)d_in[0];
    const float* embed_w   = (const float*)d_in[1];
    const float* pos_w     = (const float*)d_in[2];
    const float* qkv_w     = (const float*)d_in[3];
    const float* out_w     = (const float*)d_in[4];
    const float* norm1_w   = (const float*)d_in[5];
    const float* norm2_w   = (const float*)d_in[6];
    const float* ff_w1     = (const float*)d_in[7];
    const float* ff_w2     = (const float*)d_in[8];
    const float* ff_w3     = (const float*)d_in[9];
    const float* router_w  = (const float*)d_in[10];
    const float* lat_qkv_w = (const float*)d_in[11];
    const float* lat_out_w = (const float*)d_in[12];
    const float* lat_n1    = (const float*)d_in[13];
    const float* lat_n2    = (const float*)d_in[14];
    const float* lat_w1    = (const float*)d_in[15];
    const float* lat_w2    = (const float*)d_in[16];
    const float* lat_w3    = (const float*)d_in[17];
    const float* mem_keys  = (const float*)d_in[18];
    const float* mem_values= (const float*)d_in[19];
    const float* mem_qp    = (const float*)d_in[20];
    const float* mem_op    = (const float*)d_in[21];
    const float* gate_w1   = (const float*)d_in[22];
    const float* gate_b1   = (const float*)d_in[23];
    const float* gate_w2   = (const float*)d_in[24];
    const float* gate_b2   = (const float*)d_in[25];
    const float* final_nw  = (const float*)d_in[26];
    float* out = (float*)d_out;

    Ptrs p;
    cudaGetSymbolAddress((void**)&p.X, g_X);
    cudaGetSymbolAddress((void**)&p.Y, g_Y);
    cudaGetSymbolAddress((void**)&p.Hb, g_Hb);
    cudaGetSymbolAddress((void**)&p.QKV, g_QKV);
    cudaGetSymbolAddress((void**)&p.P, g_P);
    cudaGetSymbolAddress((void**)&p.ATT, g_ATT);
    cudaGetSymbolAddress((void**)&p.U, g_U);
    cudaGetSymbolAddress((void**)&p.V2, g_V2);
    cudaGetSymbolAddress((void**)&p.SIM, g_SIM);
    cudaGetSymbolAddress((void**)&p.RETP, g_RETP);
    cudaGetSymbolAddress((void**)&p.RET, g_RET);
    cudaGetSymbolAddress((void**)&p.GI, g_GI);
    cudaGetSymbolAddress((void**)&p.H1, g_H1);
    cudaGetSymbolAddress((void**)&p.SC, g_SC);
    cudaGetSymbolAddress((void**)&p.SEL, g_SEL);

    embed_k<<<BT_, 256>>>(ids, embed_w, pos_w, p.X);

    for (int i = 0; i < L_; i++) {
        const float* qw = qkv_w + (size_t)i * QKVD_ * D_;
        const float* ow = out_w + (size_t)i * D_ * D_;
        const float* n1 = norm1_w + (size_t)i * D_;
        const float* n2 = norm2_w + (size_t)i * D_;
        const float* w1 = ff_w1 + (size_t)i * DFF_ * D_;
        const float* w2 = ff_w2 + (size_t)i * DFF_ * D_;
        const float* w3 = ff_w3 + (size_t)i * D_ * DFF_;
        if (i % 2 == 1) {
            router_score_k<<<BT_, 256>>>(p.X, router_w + (size_t)i * D_, p.SC);
            topk_sel_k<<<B_, T_>>>(p.SC, p.SEL);
            cudaMemcpyAsync(p.Y, p.X, (size_t)BT_ * D_ * sizeof(float),
                            cudaMemcpyDeviceToDevice);
            tblock_run(p, qw, ow, n1, n2, w1, w2, w3, p.Y);
            sel_merge_k<<<BT_, 256>>>(p.X, p.Y, p.SEL);
        } else {
            tblock_run(p, qw, ow, n1, n2, w1, w2, w3, p.X);
        }
    }

    for (int it = 0; it < NLAT_; it++)
        tblock_run(p, lat_qkv_w, lat_out_w, lat_n1, lat_n2, lat_w1, lat_w2, lat_w3, p.X);

    // kNN memory retrieval
    gemm(p.X, mem_qp, p.Hb, BT_, D_, D_, false);          // q
    gemm(p.Hb, mem_keys, p.SIM, BT_, NMEM_, D_, false);   // sim (unscaled)
    memtopk_k<<<BT_, 256>>>(p.SIM, mem_values, p.RETP);
    gemm(p.RETP, mem_op, p.RET, BT_, D_, D_, false);
    concat_k<<<BT_, 256>>>(p.X, p.RET, p.GI);
    gemm(p.GI, gate_w1, p.H1, BT_, D_ / 2, 2 * D_, false);
    gelu_bias_k<<<(BT_ * (D_ / 2) + 255) / 256, 256>>>(p.H1, gate_b1, BT_ * (D_ / 2));
    gate_k<<<BT_, 256>>>(p.H1, gate_w2, gate_b2, p.RET, p.X);

    // final norm + tied LM head
    rmsnorm_k<<<BT_, 256>>>(p.X, final_nw, p.Hb);
    gemm(p.Hb, embed_w, out, BT_, VOCAB_, D_, false);
}

// round 5
// speedup vs baseline: 1.1412x; 1.1412x over previous
#include <cuda_runtime.h>
#include <cuda_bf16.h>
#include <math.h>
#include <stdint.h>

#define B_ 4
#define T_ 512
#define D_ 768
#define H_ 12
#define HD_ 64
#define L_ 12
#define DFF_ 2048
#define VOCAB_ 50257
#define NMEM_ 1024
#define TOPK_ 8
#define NLAT_ 4
#define CAP_ 64
#define BT_ (B_*T_)
#define QKVD_ (3*D_)

// ------------------- scratch (device globals; no allocation) -------------------
__device__ float g_X[BT_*D_];
__device__ float g_Y[BT_*D_];
__device__ float g_Hb[BT_*D_];
__device__ float g_QKV[BT_*QKVD_];
__device__ float g_P[(size_t)B_*H_*T_*T_];
__device__ float g_ATT[BT_*D_];
__device__ float g_U[BT_*DFF_];
__device__ float g_V2[BT_*DFF_];
__device__ float g_SIM[BT_*NMEM_];
__device__ float g_RETP[BT_*D_];
__device__ float g_RET[BT_*D_];
__device__ float g_GI[BT_*2*D_];
__device__ float g_H1[BT_*(D_/2)];
__device__ float g_SC[BT_];
__device__ int   g_SEL[BT_];

// ---- 3xTF32 tensor-core GEMM: C[M,N] = A[M,K] @ B[N,K]^T (+C), fp32-accurate ----
// Block tile 128x128, BK=16, 8 warps (2M x 4N), warp tile 64x32.
// Each operand split a = hi + lo (tf32 each); product = hi*hi + hi*lo + lo*hi.

__device__ __forceinline__ uint32_t f2tf32(float v) {
    uint32_t r;
    asm("cvt.rna.tf32.f32 %0, %1;" : "=r"(r) : "f"(v));
    return r;
}

__device__ __forceinline__ void split_tf32(float v, uint32_t& hi, uint32_t& lo) {
    hi = f2tf32(v);
    float hf = __uint_as_float(hi);
    lo = f2tf32(v - hf);
}

__device__ __forceinline__ void mma_tf32(float* c, uint32_t a0, uint32_t a1,
                                         uint32_t a2, uint32_t a3,
                                         uint32_t b0, uint32_t b1) {
    asm volatile(
        "mma.sync.aligned.m16n8k8.row.col.f32.tf32.tf32.f32 "
        "{%0,%1,%2,%3}, {%4,%5,%6,%7}, {%8,%9}, {%0,%1,%2,%3};"
        : "+f"(c[0]), "+f"(c[1]), "+f"(c[2]), "+f"(c[3])
        : "r"(a0), "r"(a1), "r"(a2), "r"(a3), "r"(b0), "r"(b1));
}

__device__ __forceinline__ void cp_async16(void* smem, const void* gmem, int src_sz) {
    uint32_t s = (uint32_t)__cvta_generic_to_shared(smem);
    asm volatile("cp.async.cg.shared.global [%0], [%1], 16, %2;"
                 :: "r"(s), "l"(gmem), "r"(src_sz));
}

#define GPAD 20  // floats per smem row (16 data + 4 pad) -> conflict-free frags

template<bool ACC, bool NGUARD>
__global__ __launch_bounds__(256) void mma_gemm_nt(const float* __restrict__ A,
                                                   const float* __restrict__ Bw,
                                                   float* __restrict__ C,
                                                   int M, int N, int K) {
    __shared__ float As[2][128 * GPAD];
    __shared__ float Bs[2][128 * GPAD];
    const int bm = blockIdx.y * 128, bn = blockIdx.x * 128;
    const int tid = threadIdx.x;
    const int wid = tid >> 5, lane = tid & 31;
    const int warp_m = wid >> 2, warp_n = wid & 3;
    const int g = lane >> 2, tg = lane & 3;

    float acc[4][4][4];
#pragma unroll
    for (int mi = 0; mi < 4; mi++)
#pragma unroll
        for (int ni = 0; ni < 4; ni++)
#pragma unroll
            for (int e = 0; e < 4; e++) acc[mi][ni][e] = 0.f;

    const int nt = K >> 4;

    auto issue = [&](int s, int k0) {
#pragma unroll
        for (int ph = 0; ph < 2; ph++) {
            int idx = tid + ph * 256;
            int r = idx >> 2, c = (idx & 3) * 4;
            cp_async16(&As[s][r * GPAD + c], A + (size_t)(bm + r) * K + k0 + c, 16);
            int bsz = (!NGUARD || (bn + r) < N) ? 16 : 0;
            cp_async16(&Bs[s][r * GPAD + c], Bw + (size_t)(bn + r) * K + k0 + c, bsz);
        }
        asm volatile("cp.async.commit_group;");
    };

    issue(0, 0);
    for (int t = 0; t < nt; t++) {
        if (t + 1 < nt) {
            issue((t + 1) & 1, (t + 1) << 4);
            asm volatile("cp.async.wait_group 1;");
        } else {
            asm volatile("cp.async.wait_group 0;");
        }
        __syncthreads();
        const float* as = As[t & 1];
        const float* bs = Bs[t & 1];
#pragma unroll
        for (int k0 = 0; k0 < 16; k0 += 8) {
            uint32_t bh[4][2], bl[4][2];
#pragma unroll
            for (int ni = 0; ni < 4; ni++) {
                int rn = (warp_n * 32 + ni * 8 + g) * GPAD + k0 + tg;
                split_tf32(bs[rn], bh[ni][0], bl[ni][0]);
                split_tf32(bs[rn + 4], bh[ni][1], bl[ni][1]);
            }
#pragma unroll
            for (int mi = 0; mi < 4; mi++) {
                int rm = (warp_m * 64 + mi * 16 + g) * GPAD + k0 + tg;
                uint32_t ah[4], al[4];
                split_tf32(as[rm],               ah[0], al[0]);
                split_tf32(as[rm + 8 * GPAD],    ah[1], al[1]);
                split_tf32(as[rm + 4],           ah[2], al[2]);
                split_tf32(as[rm + 8 * GPAD + 4], ah[3], al[3]);
#pragma unroll
                for (int ni = 0; ni < 4; ni++) {
                    // lo*hi and hi*lo first (small terms), hi*hi last
                    mma_tf32(acc[mi][ni], al[0], al[1], al[2], al[3],
                             bh[ni][0], bh[ni][1]);
                    mma_tf32(acc[mi][ni], ah[0], ah[1], ah[2], ah[3],
                             bl[ni][0], bl[ni][1]);
                    mma_tf32(acc[mi][ni], ah[0], ah[1], ah[2], ah[3],
                             bh[ni][0], bh[ni][1]);
                }
            }
        }
        __syncthreads();
    }

#pragma unroll
    for (int mi = 0; mi < 4; mi++) {
#pragma unroll
        for (int ni = 0; ni < 4; ni++) {
            int row0 = bm + warp_m * 64 + mi * 16 + g;
            int col = bn + warp_n * 32 + ni * 8 + tg * 2;
#pragma unroll
            for (int rr = 0; rr < 2; rr++) {
                int row = row0 + rr * 8;
                float* cp = C + (size_t)row * N + col;
                float v0 = acc[mi][ni][rr * 2 + 0];
                float v1 = acc[mi][ni][rr * 2 + 1];
                if (!NGUARD || col + 1 < N) {
                    if (ACC) { cp[0] += v0; cp[1] += v1; }
                    else     { cp[0] = v0;  cp[1] = v1; }
                } else if (col < N) {
                    if (ACC) cp[0] += v0; else cp[0] = v0;
                }
            }
        }
    }
}

// ------------------- elementwise / small kernels -------------------
__global__ void embed_k(const int* __restrict__ ids, const float* __restrict__ E,
                        const float* __restrict__ Pw, float* __restrict__ X) {
    int m = blockIdx.x;
    int t = m % T_;
    int id = ids[m];
    for (int i = threadIdx.x; i < D_; i += 256)
        X[(size_t)m * D_ + i] = E[(size_t)id * D_ + i] + Pw[(size_t)t * D_ + i];
}

__global__ void rmsnorm_k(const float* __restrict__ X, const float* __restrict__ w,
                          float* __restrict__ Yb) {
    int m = blockIdx.x;
    const float* x = X + (size_t)m * D_;
    float s = 0.f;
    for (int i = threadIdx.x; i < D_; i += 256) { float v = x[i]; s += v * v; }
    __shared__ float red[256];
    red[threadIdx.x] = s; __syncthreads();
    for (int st = 128; st > 0; st >>= 1) {
        if (threadIdx.x < st) red[threadIdx.x] += red[threadIdx.x + st];
        __syncthreads();
    }
    float scale = rsqrtf(red[0] / (float)D_ + 1e-6f);
    for (int i = threadIdx.x; i < D_; i += 256)
        Yb[(size_t)m * D_ + i] = x[i] * scale * w[i];
}

__global__ void attn_softmax_k(const float* __restrict__ QKV, float* __restrict__ P) {
    int qi = blockIdx.x;
    int bh = blockIdx.y;
    int b = bh / H_, h = bh % H_;
    int tid = threadIdx.x;  // 128
    __shared__ float qs[HD_];
    __shared__ float red[128];
    const float* qrow = QKV + (size_t)(b * T_ + qi) * QKVD_ + h * HD_;
    if (tid < HD_) qs[tid] = qrow[tid];
    __syncthreads();
    int nk = qi + 1;
    float s_local[4];
    float mx = -1e30f;
    int c = 0;
    for (int k = tid; k < nk; k += 128, c++) {
        const float* krow = QKV + (size_t)(b * T_ + k) * QKVD_ + D_ + h * HD_;
        float d = 0.f;
#pragma unroll
        for (int e = 0; e < HD_; e++) d += qs[e] * krow[e];
        d *= 0.125f;
        s_local[c] = d;
        mx = fmaxf(mx, d);
    }
    red[tid] = mx; __syncthreads();
    for (int st = 64; st > 0; st >>= 1) {
        if (tid < st) red[tid] = fmaxf(red[tid], red[tid + st]);
        __syncthreads();
    }
    mx = red[0]; __syncthreads();
    float sum = 0.f;
    c = 0;
    for (int k = tid; k < nk; k += 128, c++) {
        s_local[c] = expf(s_local[c] - mx);
        sum += s_local[c];
    }
    red[tid] = sum; __syncthreads();
    for (int st = 64; st > 0; st >>= 1) {
        if (tid < st) red[tid] += red[tid + st];
        __syncthreads();
    }
    float inv = 1.f / red[0];
    float* prow = P + ((size_t)bh * T_ + qi) * T_;
    c = 0;
    for (int k = tid; k < nk; k += 128, c++) prow[k] = s_local[c] * inv;
}

__global__ void attn_av_k(const float* __restrict__ P, const float* __restrict__ QKV,
                          float* __restrict__ O) {
    int qi = blockIdx.x;
    int bh = blockIdx.y;
    int b = bh / H_, h = bh % H_;
    int tid = threadIdx.x;  // 256
    int d = tid & 63, part = tid >> 6;
    const float* prow = P + ((size_t)bh * T_ + qi) * T_;
    float acc = 0.f;
    int nk = qi + 1;
    for (int k = part; k < nk; k += 4) {
        const float* vrow = QKV + (size_t)(b * T_ + k) * QKVD_ + 2 * D_ + h * HD_;
        acc += prow[k] * vrow[d];
    }
    __shared__ float sh[256];
    sh[tid] = acc; __syncthreads();
    if (part == 0) {
        float r = sh[d] + sh[d + 64] + sh[d + 128] + sh[d + 192];
        O[(size_t)(b * T_ + qi) * D_ + h * HD_ + d] = r;
    }
}

__global__ void swiglu_k(float* __restrict__ U, const float* __restrict__ V, int n) {
    int i = blockIdx.x * blockDim.x + threadIdx.x;
    if (i < n) {
        float u = U[i];
        float s = u / (1.f + expf(-u));
        U[i] = s * V[i];
    }
}

__global__ void router_score_k(const float* __restrict__ X, const float* __restrict__ rw,
                               float* __restrict__ sc) {
    int m = blockIdx.x;
    float s = 0.f;
    for (int i = threadIdx.x; i < D_; i += 256) s += X[(size_t)m * D_ + i] * rw[i];
    __shared__ float red[256];
    red[threadIdx.x] = s; __syncthreads();
    for (int st = 128; st > 0; st >>= 1) {
        if (threadIdx.x < st) red[threadIdx.x] += red[threadIdx.x + st];
        __syncthreads();
    }
    if (threadIdx.x == 0) sc[m] = red[0];
}

__global__ void topk_sel_k(const float* __restrict__ sc, int* __restrict__ sel) {
    int b = blockIdx.x, t = threadIdx.x;  // 512 threads
    __shared__ float s[T_];
    s[t] = sc[b * T_ + t];
    __syncthreads();
    float mine = s[t];
    int rank = 0;
    for (int j = 0; j < T_; j++) {
        float v = s[j];
        if (v > mine || (v == mine && j < t)) rank++;
    }
    sel[b * T_ + t] = (rank < CAP_) ? 1 : 0;
}

__global__ void sel_merge_k(float* __restrict__ X, const float* __restrict__ Y,
                            const int* __restrict__ sel) {
    int m = blockIdx.x;
    if (sel[m]) {
        for (int i = threadIdx.x; i < D_; i += 256)
            X[(size_t)m * D_ + i] = Y[(size_t)m * D_ + i];
    }
}

__global__ void memtopk_k(const float* __restrict__ SIM, const float* __restrict__ MV,
                          float* __restrict__ RETP) {
    int m = blockIdx.x;
    int tid = threadIdx.x;  // 256
    __shared__ float s[NMEM_];
    __shared__ float wts[TOPK_];
    __shared__ int idxs[TOPK_];
    __shared__ float rv[256];
    __shared__ int ri[256];
    const float invs = 0.03608439182435161f;  // 1/sqrt(768)
    for (int i = tid; i < NMEM_; i += 256) s[i] = SIM[(size_t)m * NMEM_ + i] * invs;
    __syncthreads();
    for (int j = 0; j < TOPK_; j++) {
        float bv = -1e30f; int bi = 0x7fffffff;
        for (int i = tid; i < NMEM_; i += 256) {
            if (s[i] > bv) { bv = s[i]; bi = i; }
        }
        rv[tid] = bv; ri[tid] = bi; __syncthreads();
        for (int st = 128; st > 0; st >>= 1) {
            if (tid < st) {
                if (rv[tid + st] > rv[tid] ||
                    (rv[tid + st] == rv[tid] && ri[tid + st] < ri[tid])) {
                    rv[tid] = rv[tid + st]; ri[tid] = ri[tid + st];
                }
            }
            __syncthreads();
        }
        if (tid == 0) { wts[j] = rv[0]; idxs[j] = ri[0]; s[ri[0]] = -1e30f; }
        __syncthreads();
    }
    if (tid == 0) {
        float mx = wts[0];
        float sum = 0.f;
        for (int j = 0; j < TOPK_; j++) { wts[j] = expf(wts[j] - mx); sum += wts[j]; }
        float inv = 1.f / sum;
        for (int j = 0; j < TOPK_; j++) wts[j] *= inv;
    }
    __syncthreads();
    for (int i = tid; i < D_; i += 256) {
        float a = 0.f;
#pragma unroll
        for (int j = 0; j < TOPK_; j++) a += wts[j] * MV[(size_t)idxs[j] * D_ + i];
        RETP[(size_t)m * D_ + i] = a;
    }
}

__global__ void concat_k(const float* __restrict__ X, const float* __restrict__ RET,
                         float* __restrict__ GI) {
    int m = blockIdx.x;
    for (int i = threadIdx.x; i < D_; i += 256) {
        GI[(size_t)m * 2 * D_ + i] = X[(size_t)m * D_ + i];
        GI[(size_t)m * 2 * D_ + D_ + i] = RET[(size_t)m * D_ + i];
    }
}

__global__ void gelu_bias_k(float* __restrict__ H1, const float* __restrict__ b1, int n) {
    int i = blockIdx.x * blockDim.x + threadIdx.x;
    if (i < n) {
        int col = i % (D_ / 2);
        float v = H1[i] + b1[col];
        H1[i] = 0.5f * v * (1.f + erff(v * 0.70710678118654752f));
    }
}

__global__ void gate_k(const float* __restrict__ H1, const float* __restrict__ w2,
                       const float* __restrict__ b2, const float* __restrict__ RET,
                       float* __restrict__ X) {
    int m = blockIdx.x;
    float s = 0.f;
    for (int i = threadIdx.x; i < D_ / 2; i += 256)
        s += H1[(size_t)m * (D_ / 2) + i] * w2[i];
    __shared__ float red[256];
    red[threadIdx.x] = s; __syncthreads();
    for (int st = 128; st > 0; st >>= 1) {
        if (threadIdx.x < st) red[threadIdx.x] += red[threadIdx.x + st];
        __syncthreads();
    }
    __shared__ float gsh;
    if (threadIdx.x == 0) gsh = 1.f / (1.f + expf(-(red[0] + b2[0])));
    __syncthreads();
    float g = gsh;
    for (int i = threadIdx.x; i < D_; i += 256)
        X[(size_t)m * D_ + i] += g * RET[(size_t)m * D_ + i];
}

// ------------------- host orchestration -------------------
static void gemm(const float* A, const float* Bw, float* C, int M, int N, int K, bool acc) {
    dim3 grid((N + 127) / 128, M / 128);
    if (N % 128 == 0) {
        if (acc) mma_gemm_nt<true, false><<<grid, 256>>>(A, Bw, C, M, N, K);
        else     mma_gemm_nt<false, false><<<grid, 256>>>(A, Bw, C, M, N, K);
    } else {
        if (acc) mma_gemm_nt<true, true><<<grid, 256>>>(A, Bw, C, M, N, K);
        else     mma_gemm_nt<false, true><<<grid, 256>>>(A, Bw, C, M, N, K);
    }
}

struct Ptrs {
    float *X, *Y, *Hb, *QKV, *P, *ATT, *U, *V2, *SIM, *RETP, *RET, *GI, *H1, *SC;
    int* SEL;
};

static void tblock_run(const Ptrs& p, const float* qkv_w, const float* out_w,
                       const float* n1, const float* n2, const float* w1,
                       const float* w2, const float* w3, float* x) {
    rmsnorm_k<<<BT_, 256>>>(x, n1, p.Hb);
    gemm(p.Hb, qkv_w, p.QKV, BT_, QKVD_, D_, false);
    attn_softmax_k<<<dim3(T_, B_ * H_), 128>>>(p.QKV, p.P);
    attn_av_k<<<dim3(T_, B_ * H_), 256>>>(p.P, p.QKV, p.ATT);
    gemm(p.ATT, out_w, x, BT_, D_, D_, true);
    rmsnorm_k<<<BT_, 256>>>(x, n2, p.Hb);
    gemm(p.Hb, w1, p.U, BT_, DFF_, D_, false);
    gemm(p.Hb, w2, p.V2, BT_, DFF_, D_, false);
    swiglu_k<<<(BT_ * DFF_ + 255) / 256, 256>>>(p.U, p.V2, BT_ * DFF_);
    gemm(p.U, w3, x, BT_, D_, DFF_, true);
}

extern "C" void kernel_launch(void* const* d_in, const int* in_sizes, int n_in,
                              void* d_out, int out_size) {
    const int*   ids       = (const int*)d_in[0];
    const float* embed_w   = (const float*)d_in[1];
    const float* pos_w     = (const float*)d_in[2];
    const float* qkv_w     = (const float*)d_in[3];
    const float* out_w     = (const float*)d_in[4];
    const float* norm1_w   = (const float*)d_in[5];
    const float* norm2_w   = (const float*)d_in[6];
    const float* ff_w1     = (const float*)d_in[7];
    const float* ff_w2     = (const float*)d_in[8];
    const float* ff_w3     = (const float*)d_in[9];
    const float* router_w  = (const float*)d_in[10];
    const float* lat_qkv_w = (const float*)d_in[11];
    const float* lat_out_w = (const float*)d_in[12];
    const float* lat_n1    = (const float*)d_in[13];
    const float* lat_n2    = (const float*)d_in[14];
    const float* lat_w1    = (const float*)d_in[15];
    const float* lat_w2    = (const float*)d_in[16];
    const float* lat_w3    = (const float*)d_in[17];
    const float* mem_keys  = (const float*)d_in[18];
    const float* mem_values= (const float*)d_in[19];
    const float* mem_qp    = (const float*)d_in[20];
    const float* mem_op    = (const float*)d_in[21];
    const float* gate_w1   = (const float*)d_in[22];
    const float* gate_b1   = (const float*)d_in[23];
    const float* gate_w2   = (const float*)d_in[24];
    const float* gate_b2   = (const float*)d_in[25];
    const float* final_nw  = (const float*)d_in[26];
    float* out = (float*)d_out;

    Ptrs p;
    cudaGetSymbolAddress((void**)&p.X, g_X);
    cudaGetSymbolAddress((void**)&p.Y, g_Y);
    cudaGetSymbolAddress((void**)&p.Hb, g_Hb);
    cudaGetSymbolAddress((void**)&p.QKV, g_QKV);
    cudaGetSymbolAddress((void**)&p.P, g_P);
    cudaGetSymbolAddress((void**)&p.ATT, g_ATT);
    cudaGetSymbolAddress((void**)&p.U, g_U);
    cudaGetSymbolAddress((void**)&p.V2, g_V2);
    cudaGetSymbolAddress((void**)&p.SIM, g_SIM);
    cudaGetSymbolAddress((void**)&p.RETP, g_RETP);
    cudaGetSymbolAddress((void**)&p.RET, g_RET);
    cudaGetSymbolAddress((void**)&p.GI, g_GI);
    cudaGetSymbolAddress((void**)&p.H1, g_H1);
    cudaGetSymbolAddress((void**)&p.SC, g_SC);
    cudaGetSymbolAddress((void**)&p.SEL, g_SEL);

    embed_k<<<BT_, 256>>>(ids, embed_w, pos_w, p.X);

    for (int i = 0; i < L_; i++) {
        const float* qw = qkv_w + (size_t)i * QKVD_ * D_;
        const float* ow = out_w + (size_t)i * D_ * D_;
        const float* n1 = norm1_w + (size_t)i * D_;
        const float* n2 = norm2_w + (size_t)i * D_;
        const float* w1 = ff_w1 + (size_t)i * DFF_ * D_;
        const float* w2 = ff_w2 + (size_t)i * DFF_ * D_;
        const float* w3 = ff_w3 + (size_t)i * D_ * DFF_;
        if (i % 2 == 1) {
            router_score_k<<<BT_, 256>>>(p.X, router_w + (size_t)i * D_, p.SC);
            topk_sel_k<<<B_, T_>>>(p.SC, p.SEL);
            cudaMemcpyAsync(p.Y, p.X, (size_t)BT_ * D_ * sizeof(float),
                            cudaMemcpyDeviceToDevice);
            tblock_run(p, qw, ow, n1, n2, w1, w2, w3, p.Y);
            sel_merge_k<<<BT_, 256>>>(p.X, p.Y, p.SEL);
        } else {
            tblock_run(p, qw, ow, n1, n2, w1, w2, w3, p.X);
        }
    }

    for (int it = 0; it < NLAT_; it++)
        tblock_run(p, lat_qkv_w, lat_out_w, lat_n1, lat_n2, lat_w1, lat_w2, lat_w3, p.X);

    // kNN memory retrieval
    gemm(p.X, mem_qp, p.Hb, BT_, D_, D_, false);          // q
    gemm(p.Hb, mem_keys, p.SIM, BT_, NMEM_, D_, false);   // sim (unscaled)
    memtopk_k<<<BT_, 256>>>(p.SIM, mem_values, p.RETP);
    gemm(p.RETP, mem_op, p.RET, BT_, D_, D_, false);
    concat_k<<<BT_, 256>>>(p.X, p.RET, p.GI);
    gemm(p.GI, gate_w1, p.H1, BT_, D_ / 2, 2 * D_, false);
    gelu_bias_k<<<(BT_ * (D_ / 2) + 255) / 256, 256>>>(p.H1, gate_b1, BT_ * (D_ / 2));
    gate_k<<<BT_, 256>>>(p.H1, gate_w2, gate_b2, p.RET, p.X);

    // final norm + tied LM head
    rmsnorm_k<<<BT_, 256>>>(p.X, final_nw, p.Hb);
    gemm(p.Hb, embed_w, out, BT_, VOCAB_, D_, false);
}

// round 9
// speedup vs baseline: 1.1710x; 1.0261x over previous
#include <cuda_runtime.h>
#include <cuda_bf16.h>
#include <math.h>
#include <stdint.h>

#define B_ 4
#define T_ 512
#define D_ 768
#define H_ 12
#define HD_ 64
#define L_ 12
#define DFF_ 2048
#define VOCAB_ 50257
#define NMEM_ 1024
#define TOPK_ 8
#define NLAT_ 4
#define CAP_ 64
#define BT_ (B_*T_)
#define QKVD_ (3*D_)

// ------------------- scratch (device globals; no allocation) -------------------
__device__ float g_X[BT_*D_];
__device__ float g_Y[BT_*D_];
__device__ float g_Hb[BT_*D_];
__device__ float g_QKV[BT_*QKVD_];
__device__ float g_P[(size_t)B_*H_*T_*T_];
__device__ float g_ATT[BT_*D_];
__device__ float g_U[BT_*DFF_];
__device__ float g_V2[BT_*DFF_];
__device__ float g_SIM[BT_*NMEM_];
__device__ float g_RETP[BT_*D_];
__device__ float g_RET[BT_*D_];
__device__ float g_GI[BT_*2*D_];
__device__ float g_H1[BT_*(D_/2)];
__device__ float g_SC[BT_];
__device__ int   g_SEL[BT_];

// ==================== 3xTF32 mma.sync GEMM, pre-split staging ====================
// C[M,N] = A[M,K] @ B[N,K]^T (+C). Block 128x128, BK=16, 8 warps (2Mx4N),
// warp tile 64x32. Staging: LDG fp32 -> split hi/lo (tf32) -> STS into 4 smem
// tiles (Ah, Al, Bh, Bl). MMA loop: pure LDS -> HMMA, no cvt on critical path.

#define GP 20                 // floats per smem row (16 data + 4 pad)
#define TILE_F (128 * GP)     // floats per tile
#define GEMM_SMEM (8 * TILE_F * 4)  // 2 stages x 4 tiles = 81920 bytes

__device__ __forceinline__ float tf32r(float v) {
    uint32_t r;
    asm("cvt.rna.tf32.f32 %0, %1;" : "=r"(r) : "f"(v));
    return __uint_as_float(r);
}

__device__ __forceinline__ void mma_tf32(float* c, uint32_t a0, uint32_t a1,
                                         uint32_t a2, uint32_t a3,
                                         uint32_t b0, uint32_t b1) {
    asm volatile(
        "mma.sync.aligned.m16n8k8.row.col.f32.tf32.tf32.f32 "
        "{%0,%1,%2,%3}, {%4,%5,%6,%7}, {%8,%9}, {%0,%1,%2,%3};"
        : "+f"(c[0]), "+f"(c[1]), "+f"(c[2]), "+f"(c[3])
        : "r"(a0), "r"(a1), "r"(a2), "r"(a3), "r"(b0), "r"(b1));
}

template<bool ACC, bool NGUARD>
__global__ __launch_bounds__(256, 2) void mma3_gemm_nt(const float* __restrict__ A,
                                                       const float* __restrict__ Bw,
                                                       float* __restrict__ C,
                                                       int M, int N, int K) {
    extern __shared__ float sm[];
    const int bm = blockIdx.y * 128, bn = blockIdx.x * 128;
    const int tid = threadIdx.x;
    const int wid = tid >> 5, lane = tid & 31;
    const int warp_m = wid >> 2, warp_n = wid & 3;
    const int g = lane >> 2, tg = lane & 3;

    float acc[4][4][4];
#pragma unroll
    for (int mi = 0; mi < 4; mi++)
#pragma unroll
        for (int ni = 0; ni < 4; ni++)
#pragma unroll
            for (int e = 0; e < 4; e++) acc[mi][ni][e] = 0.f;

    // staging coordinates: each thread owns 2 float4 per matrix
    const int r_0 = tid >> 2,       c4_0 = (tid & 3) * 4;
    const int r_1 = (tid + 256) >> 2, c4_1 = ((tid + 256) & 3) * 4;
    const float* a0p = A + (size_t)(bm + r_0) * K + c4_0;
    const float* a1p = A + (size_t)(bm + r_1) * K + c4_1;
    const bool b0ok = !NGUARD || (bn + r_0) < N;
    const bool b1ok = !NGUARD || (bn + r_1) < N;
    const float* b0p = Bw + (size_t)(bn + r_0) * K + c4_0;
    const float* b1p = Bw + (size_t)(bn + r_1) * K + c4_1;

    const int nt = K >> 4;
    float4 ra0, ra1, rb0, rb1;

    // prologue load (k0 = 0)
    ra0 = *(const float4*)(a0p);
    ra1 = *(const float4*)(a1p);
    rb0 = b0ok ? *(const float4*)(b0p) : make_float4(0.f, 0.f, 0.f, 0.f);
    rb1 = b1ok ? *(const float4*)(b1p) : make_float4(0.f, 0.f, 0.f, 0.f);

    for (int t = 0; t < nt; t++) {
        const int s = t & 1;
        float* st = sm + s * 4 * TILE_F;
        // split + STS (Ah, Al, Bh, Bl)
        {
            float hx, hy, hz, hw;
            int off = r_0 * GP + c4_0;
            hx = tf32r(ra0.x); hy = tf32r(ra0.y); hz = tf32r(ra0.z); hw = tf32r(ra0.w);
            *(float4*)(st + off) = make_float4(hx, hy, hz, hw);
            *(float4*)(st + TILE_F + off) =
                make_float4(tf32r(ra0.x - hx), tf32r(ra0.y - hy),
                            tf32r(ra0.z - hz), tf32r(ra0.w - hw));
            off = r_1 * GP + c4_1;
            hx = tf32r(ra1.x); hy = tf32r(ra1.y); hz = tf32r(ra1.z); hw = tf32r(ra1.w);
            *(float4*)(st + off) = make_float4(hx, hy, hz, hw);
            *(float4*)(st + TILE_F + off) =
                make_float4(tf32r(ra1.x - hx), tf32r(ra1.y - hy),
                            tf32r(ra1.z - hz), tf32r(ra1.w - hw));
            off = r_0 * GP + c4_0;
            hx = tf32r(rb0.x); hy = tf32r(rb0.y); hz = tf32r(rb0.z); hw = tf32r(rb0.w);
            *(float4*)(st + 2 * TILE_F + off) = make_float4(hx, hy, hz, hw);
            *(float4*)(st + 3 * TILE_F + off) =
                make_float4(tf32r(rb0.x - hx), tf32r(rb0.y - hy),
                            tf32r(rb0.z - hz), tf32r(rb0.w - hw));
            off = r_1 * GP + c4_1;
            hx = tf32r(rb1.x); hy = tf32r(rb1.y); hz = tf32r(rb1.z); hw = tf32r(rb1.w);
            *(float4*)(st + 2 * TILE_F + off) = make_float4(hx, hy, hz, hw);
            *(float4*)(st + 3 * TILE_F + off) =
                make_float4(tf32r(rb1.x - hx), tf32r(rb1.y - hy),
                            tf32r(rb1.z - hz), tf32r(rb1.w - hw));
        }
        // prefetch next tile (overlaps barrier + mma below)
        if (t + 1 < nt) {
            const int k0 = (t + 1) << 4;
            ra0 = *(const float4*)(a0p + k0);
            ra1 = *(const float4*)(a1p + k0);
            rb0 = b0ok ? *(const float4*)(b0p + k0) : make_float4(0.f, 0.f, 0.f, 0.f);
            rb1 = b1ok ? *(const float4*)(b1p + k0) : make_float4(0.f, 0.f, 0.f, 0.f);
        }
        __syncthreads();

        const float* Ah = sm + s * 4 * TILE_F;
        const float* Al = Ah + TILE_F;
        const float* Bh = Ah + 2 * TILE_F;
        const float* Bl = Ah + 3 * TILE_F;
#pragma unroll
        for (int k0 = 0; k0 < 16; k0 += 8) {
            uint32_t bhf[4][2], blf[4][2];
#pragma unroll
            for (int ni = 0; ni < 4; ni++) {
                const int rn = (warp_n * 32 + ni * 8 + g) * GP + k0 + tg;
                bhf[ni][0] = __float_as_uint(Bh[rn]);
                bhf[ni][1] = __float_as_uint(Bh[rn + 4]);
                blf[ni][0] = __float_as_uint(Bl[rn]);
                blf[ni][1] = __float_as_uint(Bl[rn + 4]);
            }
#pragma unroll
            for (int mi = 0; mi < 4; mi++) {
                const int rm = (warp_m * 64 + mi * 16 + g) * GP + k0 + tg;
                uint32_t ah0 = __float_as_uint(Ah[rm]);
                uint32_t ah1 = __float_as_uint(Ah[rm + 8 * GP]);
                uint32_t ah2 = __float_as_uint(Ah[rm + 4]);
                uint32_t ah3 = __float_as_uint(Ah[rm + 8 * GP + 4]);
                uint32_t al0 = __float_as_uint(Al[rm]);
                uint32_t al1 = __float_as_uint(Al[rm + 8 * GP]);
                uint32_t al2 = __float_as_uint(Al[rm + 4]);
                uint32_t al3 = __float_as_uint(Al[rm + 8 * GP + 4]);
#pragma unroll
                for (int ni = 0; ni < 4; ni++) {
                    mma_tf32(acc[mi][ni], al0, al1, al2, al3, bhf[ni][0], bhf[ni][1]);
                    mma_tf32(acc[mi][ni], ah0, ah1, ah2, ah3, blf[ni][0], blf[ni][1]);
                    mma_tf32(acc[mi][ni], ah0, ah1, ah2, ah3, bhf[ni][0], bhf[ni][1]);
                }
            }
        }
    }

    // epilogue
#pragma unroll
    for (int mi = 0; mi < 4; mi++) {
#pragma unroll
        for (int ni = 0; ni < 4; ni++) {
            int row0 = bm + warp_m * 64 + mi * 16 + g;
            int col = bn + warp_n * 32 + ni * 8 + tg * 2;
#pragma unroll
            for (int rr = 0; rr < 2; rr++) {
                int row = row0 + rr * 8;
                float* cp = C + (size_t)row * N + col;
                float v0 = acc[mi][ni][rr * 2 + 0];
                float v1 = acc[mi][ni][rr * 2 + 1];
                if (!NGUARD || col + 1 < N) {
                    if (ACC) { cp[0] += v0; cp[1] += v1; }
                    else     { cp[0] = v0;  cp[1] = v1; }
                } else if (col < N) {
                    if (ACC) cp[0] += v0; else cp[0] = v0;
                }
            }
        }
    }
}

// ------------------- elementwise / small kernels -------------------
__global__ void embed_k(const int* __restrict__ ids, const float* __restrict__ E,
                        const float* __restrict__ Pw, float* __restrict__ X) {
    int m = blockIdx.x;
    int t = m % T_;
    int id = ids[m];
    for (int i = threadIdx.x; i < D_; i += 256)
        X[(size_t)m * D_ + i] = E[(size_t)id * D_ + i] + Pw[(size_t)t * D_ + i];
}

__global__ void rmsnorm_k(const float* __restrict__ X, const float* __restrict__ w,
                          float* __restrict__ Yb) {
    int m = blockIdx.x;
    const float* x = X + (size_t)m * D_;
    float s = 0.f;
    for (int i = threadIdx.x; i < D_; i += 256) { float v = x[i]; s += v * v; }
    __shared__ float red[256];
    red[threadIdx.x] = s; __syncthreads();
    for (int st = 128; st > 0; st >>= 1) {
        if (threadIdx.x < st) red[threadIdx.x] += red[threadIdx.x + st];
        __syncthreads();
    }
    float scale = rsqrtf(red[0] / (float)D_ + 1e-6f);
    for (int i = threadIdx.x; i < D_; i += 256)
        Yb[(size_t)m * D_ + i] = x[i] * scale * w[i];
}

__global__ void attn_softmax_k(const float* __restrict__ QKV, float* __restrict__ P) {
    int qi = blockIdx.x;
    int bh = blockIdx.y;
    int b = bh / H_, h = bh % H_;
    int tid = threadIdx.x;  // 128
    __shared__ float qs[HD_];
    __shared__ float red[128];
    const float* qrow = QKV + (size_t)(b * T_ + qi) * QKVD_ + h * HD_;
    if (tid < HD_) qs[tid] = qrow[tid];
    __syncthreads();
    int nk = qi + 1;
    float s_local[4];
    float mx = -1e30f;
    int c = 0;
    for (int k = tid; k < nk; k += 128, c++) {
        const float* krow = QKV + (size_t)(b * T_ + k) * QKVD_ + D_ + h * HD_;
        float d = 0.f;
#pragma unroll
        for (int e = 0; e < HD_; e++) d += qs[e] * krow[e];
        d *= 0.125f;
        s_local[c] = d;
        mx = fmaxf(mx, d);
    }
    red[tid] = mx; __syncthreads();
    for (int st = 64; st > 0; st >>= 1) {
        if (tid < st) red[tid] = fmaxf(red[tid], red[tid + st]);
        __syncthreads();
    }
    mx = red[0]; __syncthreads();
    float sum = 0.f;
    c = 0;
    for (int k = tid; k < nk; k += 128, c++) {
        s_local[c] = expf(s_local[c] - mx);
        sum += s_local[c];
    }
    red[tid] = sum; __syncthreads();
    for (int st = 64; st > 0; st >>= 1) {
        if (tid < st) red[tid] += red[tid + st];
        __syncthreads();
    }
    float inv = 1.f / red[0];
    float* prow = P + ((size_t)bh * T_ + qi) * T_;
    c = 0;
    for (int k = tid; k < nk; k += 128, c++) prow[k] = s_local[c] * inv;
}

__global__ void attn_av_k(const float* __restrict__ P, const float* __restrict__ QKV,
                          float* __restrict__ O) {
    int qi = blockIdx.x;
    int bh = blockIdx.y;
    int b = bh / H_, h = bh % H_;
    int tid = threadIdx.x;  // 256
    int d = tid & 63, part = tid >> 6;
    const float* prow = P + ((size_t)bh * T_ + qi) * T_;
    float acc = 0.f;
    int nk = qi + 1;
    for (int k = part; k < nk; k += 4) {
        const float* vrow = QKV + (size_t)(b * T_ + k) * QKVD_ + 2 * D_ + h * HD_;
        acc += prow[k] * vrow[d];
    }
    __shared__ float sh[256];
    sh[tid] = acc; __syncthreads();
    if (part == 0) {
        float r = sh[d] + sh[d + 64] + sh[d + 128] + sh[d + 192];
        O[(size_t)(b * T_ + qi) * D_ + h * HD_ + d] = r;
    }
}

__global__ void swiglu_k(float* __restrict__ U, const float* __restrict__ V, int n) {
    int i = blockIdx.x * blockDim.x + threadIdx.x;
    if (i < n) {
        float u = U[i];
        float s = u / (1.f + expf(-u));
        U[i] = s * V[i];
    }
}

__global__ void router_score_k(const float* __restrict__ X, const float* __restrict__ rw,
                               float* __restrict__ sc) {
    int m = blockIdx.x;
    float s = 0.f;
    for (int i = threadIdx.x; i < D_; i += 256) s += X[(size_t)m * D_ + i] * rw[i];
    __shared__ float red[256];
    red[threadIdx.x] = s; __syncthreads();
    for (int st = 128; st > 0; st >>= 1) {
        if (threadIdx.x < st) red[threadIdx.x] += red[threadIdx.x + st];
        __syncthreads();
    }
    if (threadIdx.x == 0) sc[m] = red[0];
}

__global__ void topk_sel_k(const float* __restrict__ sc, int* __restrict__ sel) {
    int b = blockIdx.x, t = threadIdx.x;  // 512 threads
    __shared__ float s[T_];
    s[t] = sc[b * T_ + t];
    __syncthreads();
    float mine = s[t];
    int rank = 0;
    for (int j = 0; j < T_; j++) {
        float v = s[j];
        if (v > mine || (v == mine && j < t)) rank++;
    }
    sel[b * T_ + t] = (rank < CAP_) ? 1 : 0;
}

__global__ void sel_merge_k(float* __restrict__ X, const float* __restrict__ Y,
                            const int* __restrict__ sel) {
    int m = blockIdx.x;
    if (sel[m]) {
        for (int i = threadIdx.x; i < D_; i += 256)
            X[(size_t)m * D_ + i] = Y[(size_t)m * D_ + i];
    }
}

__global__ void memtopk_k(const float* __restrict__ SIM, const float* __restrict__ MV,
                          float* __restrict__ RETP) {
    int m = blockIdx.x;
    int tid = threadIdx.x;  // 256
    __shared__ float s[NMEM_];
    __shared__ float wts[TOPK_];
    __shared__ int idxs[TOPK_];
    __shared__ float rv[256];
    __shared__ int ri[256];
    const float invs = 0.03608439182435161f;  // 1/sqrt(768)
    for (int i = tid; i < NMEM_; i += 256) s[i] = SIM[(size_t)m * NMEM_ + i] * invs;
    __syncthreads();
    for (int j = 0; j < TOPK_; j++) {
        float bv = -1e30f; int bi = 0x7fffffff;
        for (int i = tid; i < NMEM_; i += 256) {
            if (s[i] > bv) { bv = s[i]; bi = i; }
        }
        rv[tid] = bv; ri[tid] = bi; __syncthreads();
        for (int st = 128; st > 0; st >>= 1) {
            if (tid < st) {
                if (rv[tid + st] > rv[tid] ||
                    (rv[tid + st] == rv[tid] && ri[tid + st] < ri[tid])) {
                    rv[tid] = rv[tid + st]; ri[tid] = ri[tid + st];
                }
            }
            __syncthreads();
        }
        if (tid == 0) { wts[j] = rv[0]; idxs[j] = ri[0]; s[ri[0]] = -1e30f; }
        __syncthreads();
    }
    if (tid == 0) {
        float mx = wts[0];
        float sum = 0.f;
        for (int j = 0; j < TOPK_; j++) { wts[j] = expf(wts[j] - mx); sum += wts[j]; }
        float inv = 1.f / sum;
        for (int j = 0; j < TOPK_; j++) wts[j] *= inv;
    }
    __syncthreads();
    for (int i = tid; i < D_; i += 256) {
        float a = 0.f;
#pragma unroll
        for (int j = 0; j < TOPK_; j++) a += wts[j] * MV[(size_t)idxs[j] * D_ + i];
        RETP[(size_t)m * D_ + i] = a;
    }
}

__global__ void concat_k(const float* __restrict__ X, const float* __restrict__ RET,
                         float* __restrict__ GI) {
    int m = blockIdx.x;
    for (int i = threadIdx.x; i < D_; i += 256) {
        GI[(size_t)m * 2 * D_ + i] = X[(size_t)m * D_ + i];
        GI[(size_t)m * 2 * D_ + D_ + i] = RET[(size_t)m * D_ + i];
    }
}

__global__ void gelu_bias_k(float* __restrict__ H1, const float* __restrict__ b1, int n) {
    int i = blockIdx.x * blockDim.x + threadIdx.x;
    if (i < n) {
        int col = i % (D_ / 2);
        float v = H1[i] + b1[col];
        H1[i] = 0.5f * v * (1.f + erff(v * 0.70710678118654752f));
    }
}

__global__ void gate_k(const float* __restrict__ H1, const float* __restrict__ w2,
                       const float* __restrict__ b2, const float* __restrict__ RET,
                       float* __restrict__ X) {
    int m = blockIdx.x;
    float s = 0.f;
    for (int i = threadIdx.x; i < D_ / 2; i += 256)
        s += H1[(size_t)m * (D_ / 2) + i] * w2[i];
    __shared__ float red[256];
    red[threadIdx.x] = s; __syncthreads();
    for (int st = 128; st > 0; st >>= 1) {
        if (threadIdx.x < st) red[threadIdx.x] += red[threadIdx.x + st];
        __syncthreads();
    }
    __shared__ float gsh;
    if (threadIdx.x == 0) gsh = 1.f / (1.f + expf(-(red[0] + b2[0])));
    __syncthreads();
    float g = gsh;
    for (int i = threadIdx.x; i < D_; i += 256)
        X[(size_t)m * D_ + i] += g * RET[(size_t)m * D_ + i];
}

// ------------------- host orchestration -------------------
static void gemm(const float* A, const float* Bw, float* C, int M, int N, int K, bool acc) {
    dim3 grid((N + 127) / 128, M / 128);
    if (N % 128 == 0) {
        if (acc) {
            cudaFuncSetAttribute(mma3_gemm_nt<true, false>,
                                 cudaFuncAttributeMaxDynamicSharedMemorySize, GEMM_SMEM);
            mma3_gemm_nt<true, false><<<grid, 256, GEMM_SMEM>>>(A, Bw, C, M, N, K);
        } else {
            cudaFuncSetAttribute(mma3_gemm_nt<false, false>,
                                 cudaFuncAttributeMaxDynamicSharedMemorySize, GEMM_SMEM);
            mma3_gemm_nt<false, false><<<grid, 256, GEMM_SMEM>>>(A, Bw, C, M, N, K);
        }
    } else {
        if (acc) {
            cudaFuncSetAttribute(mma3_gemm_nt<true, true>,
                                 cudaFuncAttributeMaxDynamicSharedMemorySize, GEMM_SMEM);
            mma3_gemm_nt<true, true><<<grid, 256, GEMM_SMEM>>>(A, Bw, C, M, N, K);
        } else {
            cudaFuncSetAttribute(mma3_gemm_nt<false, true>,
                                 cudaFuncAttributeMaxDynamicSharedMemorySize, GEMM_SMEM);
            mma3_gemm_nt<false, true><<<grid, 256, GEMM_SMEM>>>(A, Bw, C, M, N, K);
        }
    }
}

struct Ptrs {
    float *X, *Y, *Hb, *QKV, *P, *ATT, *U, *V2, *SIM, *RETP, *RET, *GI, *H1, *SC;
    int* SEL;
};

static void tblock_run(const Ptrs& p, const float* qkv_w, const float* out_w,
                       const float* n1, const float* n2, const float* w1,
                       const float* w2, const float* w3, float* x) {
    rmsnorm_k<<<BT_, 256>>>(x, n1, p.Hb);
    gemm(p.Hb, qkv_w, p.QKV, BT_, QKVD_, D_, false);
    attn_softmax_k<<<dim3(T_, B_ * H_), 128>>>(p.QKV, p.P);
    attn_av_k<<<dim3(T_, B_ * H_), 256>>>(p.P, p.QKV, p.ATT);
    gemm(p.ATT, out_w, x, BT_, D_, D_, true);
    rmsnorm_k<<<BT_, 256>>>(x, n2, p.Hb);
    gemm(p.Hb, w1, p.U, BT_, DFF_, D_, false);
    gemm(p.Hb, w2, p.V2, BT_, DFF_, D_, false);
    swiglu_k<<<(BT_ * DFF_ + 255) / 256, 256>>>(p.U, p.V2, BT_ * DFF_);
    gemm(p.U, w3, x, BT_, D_, DFF_, true);
}

extern "C" void kernel_launch(void* const* d_in, const int* in_sizes, int n_in,
                              void* d_out, int out_size) {
    const int*   ids       = (const int*)d_in[0];
    const float* embed_w   = (const float*)d_in[1];
    const float* pos_w     = (const float*)d_in[2];
    const float* qkv_w     = (const float*)d_in[3];
    const float* out_w     = (const float*)d_in[4];
    const float* norm1_w   = (const float*)d_in[5];
    const float* norm2_w   = (const float*)d_in[6];
    const float* ff_w1     = (const float*)d_in[7];
    const float* ff_w2     = (const float*)d_in[8];
    const float* ff_w3     = (const float*)d_in[9];
    const float* router_w  = (const float*)d_in[10];
    const float* lat_qkv_w = (const float*)d_in[11];
    const float* lat_out_w = (const float*)d_in[12];
    const float* lat_n1    = (const float*)d_in[13];
    const float* lat_n2    = (const float*)d_in[14];
    const float* lat_w1    = (const float*)d_in[15];
    const float* lat_w2    = (const float*)d_in[16];
    const float* lat_w3    = (const float*)d_in[17];
    const float* mem_keys  = (const float*)d_in[18];
    const float* mem_values= (const float*)d_in[19];
    const float* mem_qp    = (const float*)d_in[20];
    const float* mem_op    = (const float*)d_in[21];
    const float* gate_w1   = (const float*)d_in[22];
    const float* gate_b1   = (const float*)d_in[23];
    const float* gate_w2   = (const float*)d_in[24];
    const float* gate_b2   = (const float*)d_in[25];
    const float* final_nw  = (const float*)d_in[26];
    float* out = (float*)d_out;

    Ptrs p;
    cudaGetSymbolAddress((void**)&p.X, g_X);
    cudaGetSymbolAddress((void**)&p.Y, g_Y);
    cudaGetSymbolAddress((void**)&p.Hb, g_Hb);
    cudaGetSymbolAddress((void**)&p.QKV, g_QKV);
    cudaGetSymbolAddress((void**)&p.P, g_P);
    cudaGetSymbolAddress((void**)&p.ATT, g_ATT);
    cudaGetSymbolAddress((void**)&p.U, g_U);
    cudaGetSymbolAddress((void**)&p.V2, g_V2);
    cudaGetSymbolAddress((void**)&p.SIM, g_SIM);
    cudaGetSymbolAddress((void**)&p.RETP, g_RETP);
    cudaGetSymbolAddress((void**)&p.RET, g_RET);
    cudaGetSymbolAddress((void**)&p.GI, g_GI);
    cudaGetSymbolAddress((void**)&p.H1, g_H1);
    cudaGetSymbolAddress((void**)&p.SC, g_SC);
    cudaGetSymbolAddress((void**)&p.SEL, g_SEL);

    embed_k<<<BT_, 256>>>(ids, embed_w, pos_w, p.X);

    for (int i = 0; i < L_; i++) {
        const float* qw = qkv_w + (size_t)i * QKVD_ * D_;
        const float* ow = out_w + (size_t)i * D_ * D_;
        const float* n1 = norm1_w + (size_t)i * D_;
        const float* n2 = norm2_w + (size_t)i * D_;
        const float* w1 = ff_w1 + (size_t)i * DFF_ * D_;
        const float* w2 = ff_w2 + (size_t)i * DFF_ * D_;
        const float* w3 = ff_w3 + (size_t)i * D_ * DFF_;
        if (i % 2 == 1) {
            router_score_k<<<BT_, 256>>>(p.X, router_w + (size_t)i * D_, p.SC);
            topk_sel_k<<<B_, T_>>>(p.SC, p.SEL);
            cudaMemcpyAsync(p.Y, p.X, (size_t)BT_ * D_ * sizeof(float),
                            cudaMemcpyDeviceToDevice);
            tblock_run(p, qw, ow, n1, n2, w1, w2, w3, p.Y);
            sel_merge_k<<<BT_, 256>>>(p.X, p.Y, p.SEL);
        } else {
            tblock_run(p, qw, ow, n1, n2, w1, w2, w3, p.X);
        }
    }

    for (int it = 0; it < NLAT_; it++)
        tblock_run(p, lat_qkv_w, lat_out_w, lat_n1, lat_n2, lat_w1, lat_w2, lat_w3, p.X);

    // kNN memory retrieval
    gemm(p.X, mem_qp, p.Hb, BT_, D_, D_, false);          // q
    gemm(p.Hb, mem_keys, p.SIM, BT_, NMEM_, D_, false);   // sim (unscaled)
    memtopk_k<<<BT_, 256>>>(p.SIM, mem_values, p.RETP);
    gemm(p.RETP, mem_op, p.RET, BT_, D_, D_, false);
    concat_k<<<BT_, 256>>>(p.X, p.RET, p.GI);
    gemm(p.GI, gate_w1, p.H1, BT_, D_ / 2, 2 * D_, false);
    gelu_bias_k<<<(BT_ * (D_ / 2) + 255) / 256, 256>>>(p.H1, gate_b1, BT_ * (D_ / 2));
    gate_k<<<BT_, 256>>>(p.H1, gate_w2, gate_b2, p.RET, p.X);

    // final norm + tied LM head
    rmsnorm_k<<<BT_, 256>>>(p.X, final_nw, p.Hb);
    gemm(p.Hb, embed_w, out, BT_, VOCAB_, D_, false);
}

// round 11
// speedup vs baseline: 1.3631x; 1.1641x over previous
#include <cuda_runtime.h>
#include <cuda_bf16.h>
#include <cuda_fp16.h>
#include <math.h>
#include <stdint.h>

#define B_ 4
#define T_ 512
#define D_ 768
#define H_ 12
#define HD_ 64
#define L_ 12
#define DFF_ 2048
#define VOCAB_ 50257
#define NMEM_ 1024
#define TOPK_ 8
#define NLAT_ 4
#define CAP_ 64
#define BT_ (B_*T_)
#define QKVD_ (3*D_)

// ------------------- scratch (device globals; no allocation) -------------------
__device__ float g_X[BT_*D_];
__device__ float g_Y[BT_*D_];
__device__ float g_Hb[BT_*D_];
__device__ float g_QKV[BT_*QKVD_];
__device__ float g_P[(size_t)B_*H_*T_*T_];
__device__ float g_ATT[BT_*D_];
__device__ float g_U[BT_*DFF_];
__device__ float g_V2[BT_*DFF_];
__device__ float g_SIM[BT_*NMEM_];
__device__ float g_RETP[BT_*D_];
__device__ float g_RET[BT_*D_];
__device__ float g_GI[BT_*2*D_];
__device__ float g_H1[BT_*(D_/2)];
__device__ float g_SC[BT_];
__device__ int   g_SEL[BT_];

// ==================== 3x-split FP16 mma.sync GEMM (m16n8k16) ====================
// C[M,N] = A[M,K] @ B[N,K]^T (+C). Block 128x128, BK=16, 8 warps (2Mx4N),
// warp tile 64x32. a = ah + al (fp16 each, 11+11 mantissa bits);
// product = al*bh + ah*bl + ah*bh, fp32 accumulate -> ~2^-22 accuracy.
// Smem: 4 tiles (Ah,Al,Bh,Bl) x 2 stages, half2 rows with pitch 12 u32
// (8 data half2 + 4 pad) -> conflict-free fragment LDS.

#define PITCH2 12
#define TILE_U (128 * PITCH2)      // 1536 u32 per tile
// total static smem: 2 stages * 4 tiles * 1536 * 4B = 49152 bytes

__device__ __forceinline__ uint32_t pkh(__half a, __half b) {
    __half2 h = __halves2half2(a, b);
    return *(uint32_t*)&h;
}

__device__ __forceinline__ void mma_f16(float* c, uint32_t a0, uint32_t a1,
                                        uint32_t a2, uint32_t a3,
                                        uint32_t b0, uint32_t b1) {
    asm volatile(
        "mma.sync.aligned.m16n8k16.row.col.f32.f16.f16.f32 "
        "{%0,%1,%2,%3}, {%4,%5,%6,%7}, {%8,%9}, {%0,%1,%2,%3};"
        : "+f"(c[0]), "+f"(c[1]), "+f"(c[2]), "+f"(c[3])
        : "r"(a0), "r"(a1), "r"(a2), "r"(a3), "r"(b0), "r"(b1));
}

template<bool ACC, bool NGUARD>
__global__ __launch_bounds__(256, 2) void mmah_gemm_nt(const float* __restrict__ A,
                                                       const float* __restrict__ Bw,
                                                       float* __restrict__ C,
                                                       int M, int N, int K) {
    __shared__ uint32_t smu[2 * 4 * TILE_U];
    const int bm = blockIdx.y * 128, bn = blockIdx.x * 128;
    const int tid = threadIdx.x;
    const int wid = tid >> 5, lane = tid & 31;
    const int warp_m = wid >> 2, warp_n = wid & 3;
    const int g = lane >> 2, tg = lane & 3;

    float acc[4][4][4];
#pragma unroll
    for (int mi = 0; mi < 4; mi++)
#pragma unroll
        for (int ni = 0; ni < 4; ni++)
#pragma unroll
            for (int e = 0; e < 4; e++) acc[mi][ni][e] = 0.f;

    // staging coordinates: each thread owns 2 float4 per matrix
    const int r_0 = tid >> 2,         c4_0 = (tid & 3);
    const int r_1 = (tid + 256) >> 2, c4_1 = ((tid + 256) & 3);
    const float* a0p = A + (size_t)(bm + r_0) * K + c4_0 * 4;
    const float* a1p = A + (size_t)(bm + r_1) * K + c4_1 * 4;
    const bool b0ok = !NGUARD || (bn + r_0) < N;
    const bool b1ok = !NGUARD || (bn + r_1) < N;
    const float* b0p = Bw + (size_t)(bn + r_0) * K + c4_0 * 4;
    const float* b1p = Bw + (size_t)(bn + r_1) * K + c4_1 * 4;

    const int nt = K >> 4;
    float4 ra0, ra1, rb0, rb1;

    ra0 = *(const float4*)(a0p);
    ra1 = *(const float4*)(a1p);
    rb0 = b0ok ? *(const float4*)(b0p) : make_float4(0.f, 0.f, 0.f, 0.f);
    rb1 = b1ok ? *(const float4*)(b1p) : make_float4(0.f, 0.f, 0.f, 0.f);

    for (int t = 0; t < nt; t++) {
        const int s = t & 1;
        uint32_t* st = smu + s * 4 * TILE_U;

        // split fp32 -> (hi, lo) fp16 and store into 4 tiles
        {
            auto put = [&](uint32_t* tH, uint32_t* tL, int r, int c4, float4 v) {
                __half hx = __float2half_rn(v.x), hy = __float2half_rn(v.y);
                __half hz = __float2half_rn(v.z), hw = __float2half_rn(v.w);
                uint32_t h0 = pkh(hx, hy), h1 = pkh(hz, hw);
                uint32_t l0 = pkh(__float2half_rn(v.x - __half2float(hx)),
                                  __float2half_rn(v.y - __half2float(hy)));
                uint32_t l1 = pkh(__float2half_rn(v.z - __half2float(hz)),
                                  __float2half_rn(v.w - __half2float(hw)));
                int idx = r * PITCH2 + c4 * 2;
                *(uint2*)&tH[idx] = make_uint2(h0, h1);
                *(uint2*)&tL[idx] = make_uint2(l0, l1);
            };
            put(st,              st + TILE_U,     r_0, c4_0, ra0);
            put(st,              st + TILE_U,     r_1, c4_1, ra1);
            put(st + 2 * TILE_U, st + 3 * TILE_U, r_0, c4_0, rb0);
            put(st + 2 * TILE_U, st + 3 * TILE_U, r_1, c4_1, rb1);
        }
        // prefetch next tile (overlaps barrier + mma)
        if (t + 1 < nt) {
            const int k0 = (t + 1) << 4;
            ra0 = *(const float4*)(a0p + k0);
            ra1 = *(const float4*)(a1p + k0);
            rb0 = b0ok ? *(const float4*)(b0p + k0) : make_float4(0.f, 0.f, 0.f, 0.f);
            rb1 = b1ok ? *(const float4*)(b1p + k0) : make_float4(0.f, 0.f, 0.f, 0.f);
        }
        __syncthreads();

        const uint32_t* Ah = smu + s * 4 * TILE_U;
        const uint32_t* Al = Ah + TILE_U;
        const uint32_t* Bh = Ah + 2 * TILE_U;
        const uint32_t* Bl = Ah + 3 * TILE_U;

        uint32_t bh[4][2], bl[4][2];
#pragma unroll
        for (int ni = 0; ni < 4; ni++) {
            const int rb = (warp_n * 32 + ni * 8 + g) * PITCH2 + tg;
            bh[ni][0] = Bh[rb]; bh[ni][1] = Bh[rb + 4];
            bl[ni][0] = Bl[rb]; bl[ni][1] = Bl[rb + 4];
        }
#pragma unroll
        for (int mi = 0; mi < 4; mi++) {
            const int ra = (warp_m * 64 + mi * 16 + g) * PITCH2 + tg;
            const uint32_t ah0 = Ah[ra], ah1 = Ah[ra + 8 * PITCH2];
            const uint32_t ah2 = Ah[ra + 4], ah3 = Ah[ra + 8 * PITCH2 + 4];
            const uint32_t al0 = Al[ra], al1 = Al[ra + 8 * PITCH2];
            const uint32_t al2 = Al[ra + 4], al3 = Al[ra + 8 * PITCH2 + 4];
#pragma unroll
            for (int ni = 0; ni < 4; ni++) {
                mma_f16(acc[mi][ni], al0, al1, al2, al3, bh[ni][0], bh[ni][1]);
                mma_f16(acc[mi][ni], ah0, ah1, ah2, ah3, bl[ni][0], bl[ni][1]);
                mma_f16(acc[mi][ni], ah0, ah1, ah2, ah3, bh[ni][0], bh[ni][1]);
            }
        }
    }

    // epilogue
#pragma unroll
    for (int mi = 0; mi < 4; mi++) {
#pragma unroll
        for (int ni = 0; ni < 4; ni++) {
            int row0 = bm + warp_m * 64 + mi * 16 + g;
            int col = bn + warp_n * 32 + ni * 8 + tg * 2;
#pragma unroll
            for (int rr = 0; rr < 2; rr++) {
                int row = row0 + rr * 8;
                float* cp = C + (size_t)row * N + col;
                float v0 = acc[mi][ni][rr * 2 + 0];
                float v1 = acc[mi][ni][rr * 2 + 1];
                if (!NGUARD || col + 1 < N) {
                    if (ACC) { cp[0] += v0; cp[1] += v1; }
                    else     { cp[0] = v0;  cp[1] = v1; }
                } else if (col < N) {
                    if (ACC) cp[0] += v0; else cp[0] = v0;
                }
            }
        }
    }
}

// ------------------- elementwise / small kernels -------------------
__global__ void embed_k(const int* __restrict__ ids, const float* __restrict__ E,
                        const float* __restrict__ Pw, float* __restrict__ X) {
    int m = blockIdx.x;
    int t = m % T_;
    int id = ids[m];
    for (int i = threadIdx.x; i < D_; i += 256)
        X[(size_t)m * D_ + i] = E[(size_t)id * D_ + i] + Pw[(size_t)t * D_ + i];
}

__global__ void rmsnorm_k(const float* __restrict__ X, const float* __restrict__ w,
                          float* __restrict__ Yb) {
    int m = blockIdx.x;
    const float* x = X + (size_t)m * D_;
    float s = 0.f;
    for (int i = threadIdx.x; i < D_; i += 256) { float v = x[i]; s += v * v; }
    __shared__ float red[256];
    red[threadIdx.x] = s; __syncthreads();
    for (int st = 128; st > 0; st >>= 1) {
        if (threadIdx.x < st) red[threadIdx.x] += red[threadIdx.x + st];
        __syncthreads();
    }
    float scale = rsqrtf(red[0] / (float)D_ + 1e-6f);
    for (int i = threadIdx.x; i < D_; i += 256)
        Yb[(size_t)m * D_ + i] = x[i] * scale * w[i];
}

__global__ void attn_softmax_k(const float* __restrict__ QKV, float* __restrict__ P) {
    int qi = blockIdx.x;
    int bh = blockIdx.y;
    int b = bh / H_, h = bh % H_;
    int tid = threadIdx.x;  // 128
    __shared__ float qs[HD_];
    __shared__ float red[128];
    const float* qrow = QKV + (size_t)(b * T_ + qi) * QKVD_ + h * HD_;
    if (tid < HD_) qs[tid] = qrow[tid];
    __syncthreads();
    int nk = qi + 1;
    float s_local[4];
    float mx = -1e30f;
    int c = 0;
    for (int k = tid; k < nk; k += 128, c++) {
        const float* krow = QKV + (size_t)(b * T_ + k) * QKVD_ + D_ + h * HD_;
        float d = 0.f;
#pragma unroll
        for (int e = 0; e < HD_; e++) d += qs[e] * krow[e];
        d *= 0.125f;
        s_local[c] = d;
        mx = fmaxf(mx, d);
    }
    red[tid] = mx; __syncthreads();
    for (int st = 64; st > 0; st >>= 1) {
        if (tid < st) red[tid] = fmaxf(red[tid], red[tid + st]);
        __syncthreads();
    }
    mx = red[0]; __syncthreads();
    float sum = 0.f;
    c = 0;
    for (int k = tid; k < nk; k += 128, c++) {
        s_local[c] = expf(s_local[c] - mx);
        sum += s_local[c];
    }
    red[tid] = sum; __syncthreads();
    for (int st = 64; st > 0; st >>= 1) {
        if (tid < st) red[tid] += red[tid + st];
        __syncthreads();
    }
    float inv = 1.f / red[0];
    float* prow = P + ((size_t)bh * T_ + qi) * T_;
    c = 0;
    for (int k = tid; k < nk; k += 128, c++) prow[k] = s_local[c] * inv;
}

__global__ void attn_av_k(const float* __restrict__ P, const float* __restrict__ QKV,
                          float* __restrict__ O) {
    int qi = blockIdx.x;
    int bh = blockIdx.y;
    int b = bh / H_, h = bh % H_;
    int tid = threadIdx.x;  // 256
    int d = tid & 63, part = tid >> 6;
    const float* prow = P + ((size_t)bh * T_ + qi) * T_;
    float acc = 0.f;
    int nk = qi + 1;
    for (int k = part; k < nk; k += 4) {
        const float* vrow = QKV + (size_t)(b * T_ + k) * QKVD_ + 2 * D_ + h * HD_;
        acc += prow[k] * vrow[d];
    }
    __shared__ float sh[256];
    sh[tid] = acc; __syncthreads();
    if (part == 0) {
        float r = sh[d] + sh[d + 64] + sh[d + 128] + sh[d + 192];
        O[(size_t)(b * T_ + qi) * D_ + h * HD_ + d] = r;
    }
}

__global__ void swiglu_k(float* __restrict__ U, const float* __restrict__ V, int n) {
    int i = blockIdx.x * blockDim.x + threadIdx.x;
    if (i < n) {
        float u = U[i];
        float s = u / (1.f + expf(-u));
        U[i] = s * V[i];
    }
}

__global__ void router_score_k(const float* __restrict__ X, const float* __restrict__ rw,
                               float* __restrict__ sc) {
    int m = blockIdx.x;
    float s = 0.f;
    for (int i = threadIdx.x; i < D_; i += 256) s += X[(size_t)m * D_ + i] * rw[i];
    __shared__ float red[256];
    red[threadIdx.x] = s; __syncthreads();
    for (int st = 128; st > 0; st >>= 1) {
        if (threadIdx.x < st) red[threadIdx.x] += red[threadIdx.x + st];
        __syncthreads();
    }
    if (threadIdx.x == 0) sc[m] = red[0];
}

__global__ void topk_sel_k(const float* __restrict__ sc, int* __restrict__ sel) {
    int b = blockIdx.x, t = threadIdx.x;  // 512 threads
    __shared__ float s[T_];
    s[t] = sc[b * T_ + t];
    __syncthreads();
    float mine = s[t];
    int rank = 0;
    for (int j = 0; j < T_; j++) {
        float v = s[j];
        if (v > mine || (v == mine && j < t)) rank++;
    }
    sel[b * T_ + t] = (rank < CAP_) ? 1 : 0;
}

__global__ void sel_merge_k(float* __restrict__ X, const float* __restrict__ Y,
                            const int* __restrict__ sel) {
    int m = blockIdx.x;
    if (sel[m]) {
        for (int i = threadIdx.x; i < D_; i += 256)
            X[(size_t)m * D_ + i] = Y[(size_t)m * D_ + i];
    }
}

__global__ void memtopk_k(const float* __restrict__ SIM, const float* __restrict__ MV,
                          float* __restrict__ RETP) {
    int m = blockIdx.x;
    int tid = threadIdx.x;  // 256
    __shared__ float s[NMEM_];
    __shared__ float wts[TOPK_];
    __shared__ int idxs[TOPK_];
    __shared__ float rv[256];
    __shared__ int ri[256];
    const float invs = 0.03608439182435161f;  // 1/sqrt(768)
    for (int i = tid; i < NMEM_; i += 256) s[i] = SIM[(size_t)m * NMEM_ + i] * invs;
    __syncthreads();
    for (int j = 0; j < TOPK_; j++) {
        float bv = -1e30f; int bi = 0x7fffffff;
        for (int i = tid; i < NMEM_; i += 256) {
            if (s[i] > bv) { bv = s[i]; bi = i; }
        }
        rv[tid] = bv; ri[tid] = bi; __syncthreads();
        for (int st = 128; st > 0; st >>= 1) {
            if (tid < st) {
                if (rv[tid + st] > rv[tid] ||
                    (rv[tid + st] == rv[tid] && ri[tid + st] < ri[tid])) {
                    rv[tid] = rv[tid + st]; ri[tid] = ri[tid + st];
                }
            }
            __syncthreads();
        }
        if (tid == 0) { wts[j] = rv[0]; idxs[j] = ri[0]; s[ri[0]] = -1e30f; }
        __syncthreads();
    }
    if (tid == 0) {
        float mx = wts[0];
        float sum = 0.f;
        for (int j = 0; j < TOPK_; j++) { wts[j] = expf(wts[j] - mx); sum += wts[j]; }
        float inv = 1.f / sum;
        for (int j = 0; j < TOPK_; j++) wts[j] *= inv;
    }
    __syncthreads();
    for (int i = tid; i < D_; i += 256) {
        float a = 0.f;
#pragma unroll
        for (int j = 0; j < TOPK_; j++) a += wts[j] * MV[(size_t)idxs[j] * D_ + i];
        RETP[(size_t)m * D_ + i] = a;
    }
}

__global__ void concat_k(const float* __restrict__ X, const float* __restrict__ RET,
                         float* __restrict__ GI) {
    int m = blockIdx.x;
    for (int i = threadIdx.x; i < D_; i += 256) {
        GI[(size_t)m * 2 * D_ + i] = X[(size_t)m * D_ + i];
        GI[(size_t)m * 2 * D_ + D_ + i] = RET[(size_t)m * D_ + i];
    }
}

__global__ void gelu_bias_k(float* __restrict__ H1, const float* __restrict__ b1, int n) {
    int i = blockIdx.x * blockDim.x + threadIdx.x;
    if (i < n) {
        int col = i % (D_ / 2);
        float v = H1[i] + b1[col];
        H1[i] = 0.5f * v * (1.f + erff(v * 0.70710678118654752f));
    }
}

__global__ void gate_k(const float* __restrict__ H1, const float* __restrict__ w2,
                       const float* __restrict__ b2, const float* __restrict__ RET,
                       float* __restrict__ X) {
    int m = blockIdx.x;
    float s = 0.f;
    for (int i = threadIdx.x; i < D_ / 2; i += 256)
        s += H1[(size_t)m * (D_ / 2) + i] * w2[i];
    __shared__ float red[256];
    red[threadIdx.x] = s; __syncthreads();
    for (int st = 128; st > 0; st >>= 1) {
        if (threadIdx.x < st) red[threadIdx.x] += red[threadIdx.x + st];
        __syncthreads();
    }
    __shared__ float gsh;
    if (threadIdx.x == 0) gsh = 1.f / (1.f + expf(-(red[0] + b2[0])));
    __syncthreads();
    float g = gsh;
    for (int i = threadIdx.x; i < D_; i += 256)
        X[(size_t)m * D_ + i] += g * RET[(size_t)m * D_ + i];
}

// ------------------- host orchestration -------------------
static void gemm(const float* A, const float* Bw, float* C, int M, int N, int K, bool acc) {
    dim3 grid((N + 127) / 128, M / 128);
    if (N % 128 == 0) {
        if (acc) mmah_gemm_nt<true, false><<<grid, 256>>>(A, Bw, C, M, N, K);
        else     mmah_gemm_nt<false, false><<<grid, 256>>>(A, Bw, C, M, N, K);
    } else {
        if (acc) mmah_gemm_nt<true, true><<<grid, 256>>>(A, Bw, C, M, N, K);
        else     mmah_gemm_nt<false, true><<<grid, 256>>>(A, Bw, C, M, N, K);
    }
}

struct Ptrs {
    float *X, *Y, *Hb, *QKV, *P, *ATT, *U, *V2, *SIM, *RETP, *RET, *GI, *H1, *SC;
    int* SEL;
};

static void tblock_run(const Ptrs& p, const float* qkv_w, const float* out_w,
                       const float* n1, const float* n2, const float* w1,
                       const float* w2, const float* w3, float* x) {
    rmsnorm_k<<<BT_, 256>>>(x, n1, p.Hb);
    gemm(p.Hb, qkv_w, p.QKV, BT_, QKVD_, D_, false);
    attn_softmax_k<<<dim3(T_, B_ * H_), 128>>>(p.QKV, p.P);
    attn_av_k<<<dim3(T_, B_ * H_), 256>>>(p.P, p.QKV, p.ATT);
    gemm(p.ATT, out_w, x, BT_, D_, D_, true);
    rmsnorm_k<<<BT_, 256>>>(x, n2, p.Hb);
    gemm(p.Hb, w1, p.U, BT_, DFF_, D_, false);
    gemm(p.Hb, w2, p.V2, BT_, DFF_, D_, false);
    swiglu_k<<<(BT_ * DFF_ + 255) / 256, 256>>>(p.U, p.V2, BT_ * DFF_);
    gemm(p.U, w3, x, BT_, D_, DFF_, true);
}

extern "C" void kernel_launch(void* const* d_in, const int* in_sizes, int n_in,
                              void* d_out, int out_size) {
    const int*   ids       = (const int*)d_in[0];
    const float* embed_w   = (const float*)d_in[1];
    const float* pos_w     = (const float*)d_in[2];
    const float* qkv_w     = (const float*)d_in[3];
    const float* out_w     = (const float*)d_in[4];
    const float* norm1_w   = (const float*)d_in[5];
    const float* norm2_w   = (const float*)d_in[6];
    const float* ff_w1     = (const float*)d_in[7];
    const float* ff_w2     = (const float*)d_in[8];
    const float* ff_w3     = (const float*)d_in[9];
    const float* router_w  = (const float*)d_in[10];
    const float* lat_qkv_w = (const float*)d_in[11];
    const float* lat_out_w = (const float*)d_in[12];
    const float* lat_n1    = (const float*)d_in[13];
    const float* lat_n2    = (const float*)d_in[14];
    const float* lat_w1    = (const float*)d_in[15];
    const float* lat_w2    = (const float*)d_in[16];
    const float* lat_w3    = (const float*)d_in[17];
    const float* mem_keys  = (const float*)d_in[18];
    const float* mem_values= (const float*)d_in[19];
    const float* mem_qp    = (const float*)d_in[20];
    const float* mem_op    = (const float*)d_in[21];
    const float* gate_w1   = (const float*)d_in[22];
    const float* gate_b1   = (const float*)d_in[23];
    const float* gate_w2   = (const float*)d_in[24];
    const float* gate_b2   = (const float*)d_in[25];
    const float* final_nw  = (const float*)d_in[26];
    float* out = (float*)d_out;

    Ptrs p;
    cudaGetSymbolAddress((void**)&p.X, g_X);
    cudaGetSymbolAddress((void**)&p.Y, g_Y);
    cudaGetSymbolAddress((void**)&p.Hb, g_Hb);
    cudaGetSymbolAddress((void**)&p.QKV, g_QKV);
    cudaGetSymbolAddress((void**)&p.P, g_P);
    cudaGetSymbolAddress((void**)&p.ATT, g_ATT);
    cudaGetSymbolAddress((void**)&p.U, g_U);
    cudaGetSymbolAddress((void**)&p.V2, g_V2);
    cudaGetSymbolAddress((void**)&p.SIM, g_SIM);
    cudaGetSymbolAddress((void**)&p.RETP, g_RETP);
    cudaGetSymbolAddress((void**)&p.RET, g_RET);
    cudaGetSymbolAddress((void**)&p.GI, g_GI);
    cudaGetSymbolAddress((void**)&p.H1, g_H1);
    cudaGetSymbolAddress((void**)&p.SC, g_SC);
    cudaGetSymbolAddress((void**)&p.SEL, g_SEL);

    embed_k<<<BT_, 256>>>(ids, embed_w, pos_w, p.X);

    for (int i = 0; i < L_; i++) {
        const float* qw = qkv_w + (size_t)i * QKVD_ * D_;
        const float* ow = out_w + (size_t)i * D_ * D_;
        const float* n1 = norm1_w + (size_t)i * D_;
        const float* n2 = norm2_w + (size_t)i * D_;
        const float* w1 = ff_w1 + (size_t)i * DFF_ * D_;
        const float* w2 = ff_w2 + (size_t)i * DFF_ * D_;
        const float* w3 = ff_w3 + (size_t)i * D_ * DFF_;
        if (i % 2 == 1) {
            router_score_k<<<BT_, 256>>>(p.X, router_w + (size_t)i * D_, p.SC);
            topk_sel_k<<<B_, T_>>>(p.SC, p.SEL);
            cudaMemcpyAsync(p.Y, p.X, (size_t)BT_ * D_ * sizeof(float),
                            cudaMemcpyDeviceToDevice);
            tblock_run(p, qw, ow, n1, n2, w1, w2, w3, p.Y);
            sel_merge_k<<<BT_, 256>>>(p.X, p.Y, p.SEL);
        } else {
            tblock_run(p, qw, ow, n1, n2, w1, w2, w3, p.X);
        }
    }

    for (int it = 0; it < NLAT_; it++)
        tblock_run(p, lat_qkv_w, lat_out_w, lat_n1, lat_n2, lat_w1, lat_w2, lat_w3, p.X);

    // kNN memory retrieval
    gemm(p.X, mem_qp, p.Hb, BT_, D_, D_, false);          // q
    gemm(p.Hb, mem_keys, p.SIM, BT_, NMEM_, D_, false);   // sim (unscaled)
    memtopk_k<<<BT_, 256>>>(p.SIM, mem_values, p.RETP);
    gemm(p.RETP, mem_op, p.RET, BT_, D_, D_, false);
    concat_k<<<BT_, 256>>>(p.X, p.RET, p.GI);
    gemm(p.GI, gate_w1, p.H1, BT_, D_ / 2, 2 * D_, false);
    gelu_bias_k<<<(BT_ * (D_ / 2) + 255) / 256, 256>>>(p.H1, gate_b1, BT_ * (D_ / 2));
    gate_k<<<BT_, 256>>>(p.H1, gate_w2, gate_b2, p.RET, p.X);

    // final norm + tied LM head
    rmsnorm_k<<<BT_, 256>>>(p.X, final_nw, p.Hb);
    gemm(p.Hb, embed_w, out, BT_, VOCAB_, D_, false);
}

// round 12
// speedup vs baseline: 3.6864x; 2.7046x over previous
#include <cuda_runtime.h>
#include <cuda_bf16.h>
#include <cuda_fp16.h>
#include <math.h>
#include <stdint.h>

#define B_ 4
#define T_ 512
#define D_ 768
#define H_ 12
#define HD_ 64
#define L_ 12
#define DFF_ 2048
#define VOCAB_ 50257
#define NMEM_ 1024
#define TOPK_ 8
#define NLAT_ 4
#define CAP_ 64
#define BT_ (B_*T_)
#define QKVD_ (3*D_)
#define BC_ (B_*CAP_)   // 256 compacted rows

// ------------------- scratch (device globals; no allocation) -------------------
__device__ float g_X[BT_*D_];
__device__ float g_Y[BT_*D_];        // compacted residual rows (BC_ used)
__device__ float g_Hb[BT_*D_];
__device__ float g_QKV[BT_*QKVD_];   // QKV (full) or KV + Qc (MoD)
__device__ float g_ATT[BT_*D_];
__device__ float g_U[BT_*DFF_];
__device__ float g_V2[BT_*DFF_];
__device__ float g_SIM[BT_*NMEM_];
__device__ float g_RETP[BT_*D_];
__device__ float g_RET[BT_*D_];
__device__ float g_GI[BT_*2*D_];
__device__ float g_H1[BT_*(D_/2)];
__device__ float g_SC[BT_];
__device__ int   g_CIDX[BT_];

// ==================== 3x-split FP16 mma.sync GEMM (m16n8k16) ====================
#define PITCH2 12
#define TILE_U (128 * PITCH2)

__device__ __forceinline__ uint32_t pkh(__half a, __half b) {
    __half2 h = __halves2half2(a, b);
    return *(uint32_t*)&h;
}

__device__ __forceinline__ void mma_f16(float* c, uint32_t a0, uint32_t a1,
                                        uint32_t a2, uint32_t a3,
                                        uint32_t b0, uint32_t b1) {
    asm volatile(
        "mma.sync.aligned.m16n8k16.row.col.f32.f16.f16.f32 "
        "{%0,%1,%2,%3}, {%4,%5,%6,%7}, {%8,%9}, {%0,%1,%2,%3};"
        : "+f"(c[0]), "+f"(c[1]), "+f"(c[2]), "+f"(c[3])
        : "r"(a0), "r"(a1), "r"(a2), "r"(a3), "r"(b0), "r"(b1));
}

template<bool ACC, bool NGUARD>
__global__ __launch_bounds__(256, 2) void mmah_gemm_nt(const float* __restrict__ A,
                                                       const float* __restrict__ Bw,
                                                       float* __restrict__ C,
                                                       int M, int N, int K) {
    __shared__ uint32_t smu[2 * 4 * TILE_U];
    const int bm = blockIdx.y * 128, bn = blockIdx.x * 128;
    const int tid = threadIdx.x;
    const int wid = tid >> 5, lane = tid & 31;
    const int warp_m = wid >> 2, warp_n = wid & 3;
    const int g = lane >> 2, tg = lane & 3;

    float acc[4][4][4];
#pragma unroll
    for (int mi = 0; mi < 4; mi++)
#pragma unroll
        for (int ni = 0; ni < 4; ni++)
#pragma unroll
            for (int e = 0; e < 4; e++) acc[mi][ni][e] = 0.f;

    const int r_0 = tid >> 2,         c4_0 = (tid & 3);
    const int r_1 = (tid + 256) >> 2, c4_1 = ((tid + 256) & 3);
    const float* a0p = A + (size_t)(bm + r_0) * K + c4_0 * 4;
    const float* a1p = A + (size_t)(bm + r_1) * K + c4_1 * 4;
    const bool b0ok = !NGUARD || (bn + r_0) < N;
    const bool b1ok = !NGUARD || (bn + r_1) < N;
    const float* b0p = Bw + (size_t)(bn + r_0) * K + c4_0 * 4;
    const float* b1p = Bw + (size_t)(bn + r_1) * K + c4_1 * 4;

    const int nt = K >> 4;
    float4 ra0, ra1, rb0, rb1;

    ra0 = *(const float4*)(a0p);
    ra1 = *(const float4*)(a1p);
    rb0 = b0ok ? *(const float4*)(b0p) : make_float4(0.f, 0.f, 0.f, 0.f);
    rb1 = b1ok ? *(const float4*)(b1p) : make_float4(0.f, 0.f, 0.f, 0.f);

    for (int t = 0; t < nt; t++) {
        const int s = t & 1;
        uint32_t* st = smu + s * 4 * TILE_U;
        {
            auto put = [&](uint32_t* tH, uint32_t* tL, int r, int c4, float4 v) {
                __half hx = __float2half_rn(v.x), hy = __float2half_rn(v.y);
                __half hz = __float2half_rn(v.z), hw = __float2half_rn(v.w);
                uint32_t h0 = pkh(hx, hy), h1 = pkh(hz, hw);
                uint32_t l0 = pkh(__float2half_rn(v.x - __half2float(hx)),
                                  __float2half_rn(v.y - __half2float(hy)));
                uint32_t l1 = pkh(__float2half_rn(v.z - __half2float(hz)),
                                  __float2half_rn(v.w - __half2float(hw)));
                int idx = r * PITCH2 + c4 * 2;
                *(uint2*)&tH[idx] = make_uint2(h0, h1);
                *(uint2*)&tL[idx] = make_uint2(l0, l1);
            };
            put(st,              st + TILE_U,     r_0, c4_0, ra0);
            put(st,              st + TILE_U,     r_1, c4_1, ra1);
            put(st + 2 * TILE_U, st + 3 * TILE_U, r_0, c4_0, rb0);
            put(st + 2 * TILE_U, st + 3 * TILE_U, r_1, c4_1, rb1);
        }
        if (t + 1 < nt) {
            const int k0 = (t + 1) << 4;
            ra0 = *(const float4*)(a0p + k0);
            ra1 = *(const float4*)(a1p + k0);
            rb0 = b0ok ? *(const float4*)(b0p + k0) : make_float4(0.f, 0.f, 0.f, 0.f);
            rb1 = b1ok ? *(const float4*)(b1p + k0) : make_float4(0.f, 0.f, 0.f, 0.f);
        }
        __syncthreads();

        const uint32_t* Ah = smu + s * 4 * TILE_U;
        const uint32_t* Al = Ah + TILE_U;
        const uint32_t* Bh = Ah + 2 * TILE_U;
        const uint32_t* Bl = Ah + 3 * TILE_U;

        uint32_t bh[4][2], bl[4][2];
#pragma unroll
        for (int ni = 0; ni < 4; ni++) {
            const int rb = (warp_n * 32 + ni * 8 + g) * PITCH2 + tg;
            bh[ni][0] = Bh[rb]; bh[ni][1] = Bh[rb + 4];
            bl[ni][0] = Bl[rb]; bl[ni][1] = Bl[rb + 4];
        }
#pragma unroll
        for (int mi = 0; mi < 4; mi++) {
            const int ra = (warp_m * 64 + mi * 16 + g) * PITCH2 + tg;
            const uint32_t ah0 = Ah[ra], ah1 = Ah[ra + 8 * PITCH2];
            const uint32_t ah2 = Ah[ra + 4], ah3 = Ah[ra + 8 * PITCH2 + 4];
            const uint32_t al0 = Al[ra], al1 = Al[ra + 8 * PITCH2];
            const uint32_t al2 = Al[ra + 4], al3 = Al[ra + 8 * PITCH2 + 4];
#pragma unroll
            for (int ni = 0; ni < 4; ni++) {
                mma_f16(acc[mi][ni], al0, al1, al2, al3, bh[ni][0], bh[ni][1]);
                mma_f16(acc[mi][ni], ah0, ah1, ah2, ah3, bl[ni][0], bl[ni][1]);
                mma_f16(acc[mi][ni], ah0, ah1, ah2, ah3, bh[ni][0], bh[ni][1]);
            }
        }
    }

#pragma unroll
    for (int mi = 0; mi < 4; mi++) {
#pragma unroll
        for (int ni = 0; ni < 4; ni++) {
            int row0 = bm + warp_m * 64 + mi * 16 + g;
            int col = bn + warp_n * 32 + ni * 8 + tg * 2;
#pragma unroll
            for (int rr = 0; rr < 2; rr++) {
                int row = row0 + rr * 8;
                float* cp = C + (size_t)row * N + col;
                float v0 = acc[mi][ni][rr * 2 + 0];
                float v1 = acc[mi][ni][rr * 2 + 1];
                if (!NGUARD || col + 1 < N) {
                    if (ACC) { cp[0] += v0; cp[1] += v1; }
                    else     { cp[0] = v0;  cp[1] = v1; }
                } else if (col < N) {
                    if (ACC) cp[0] += v0; else cp[0] = v0;
                }
            }
        }
    }
}

// ==================== fused flash-style attention ====================
// Block: 256 threads; thread -> (q = tid>>2, sub = tid&3). Online softmax.
#define APITCH 68
#define FA_SMEM (4 * 64 * APITCH * 4)
#define FAM_SMEM (FA_SMEM + 64 * 4)

// Full attention: grid (T/64, B*H); QKV [BT][2304]; O [BT][768]
__global__ __launch_bounds__(256) void fattn_k(const float* __restrict__ QKV,
                                               float* __restrict__ O) {
    extern __shared__ float sm[];
    float* Qs = sm;
    float* Ks = sm + 64 * APITCH;
    float* Vs = sm + 2 * 64 * APITCH;
    float* Ps = sm + 3 * 64 * APITCH;
    const int qt = blockIdx.x, bh = blockIdx.y;
    const int b = bh / H_, h = bh % H_;
    const int tid = threadIdx.x;
    const int q0 = qt * 64;
    for (int i = tid; i < 64 * 16; i += 256) {
        int r = i >> 4, c4 = i & 15;
        *(float4*)(Qs + r * APITCH + c4 * 4) =
            *(const float4*)(QKV + (size_t)(b * T_ + q0 + r) * QKVD_ + h * HD_ + c4 * 4);
    }
    const int q = tid >> 2, sub = tid & 3;
    const int qglob = q0 + q;
    float m_i = -1e30f, l_i = 0.f;
    float acc[16];
#pragma unroll
    for (int i = 0; i < 16; i++) acc[i] = 0.f;

    for (int kt = 0; kt <= qt; kt++) {
        __syncthreads();
        for (int i = tid; i < 64 * 16; i += 256) {
            int r = i >> 4, c4 = i & 15;
            const float* src = QKV + (size_t)(b * T_ + kt * 64 + r) * QKVD_ + h * HD_ + c4 * 4;
            *(float4*)(Ks + r * APITCH + c4 * 4) = *(const float4*)(src + D_);
            *(float4*)(Vs + r * APITCH + c4 * 4) = *(const float4*)(src + 2 * D_);
        }
        __syncthreads();
        float s[16];
#pragma unroll
        for (int j = 0; j < 16; j++) s[j] = 0.f;
#pragma unroll 4
        for (int c4 = 0; c4 < 16; c4++) {
            float4 qv = *(const float4*)(Qs + q * APITCH + c4 * 4);
#pragma unroll
            for (int j = 0; j < 16; j++) {
                float4 kv = *(const float4*)(Ks + (sub + 4 * j) * APITCH + c4 * 4);
                s[j] += qv.x * kv.x + qv.y * kv.y + qv.z * kv.z + qv.w * kv.w;
            }
        }
        float tmax = -1e30f;
#pragma unroll
        for (int j = 0; j < 16; j++) {
            int kg = kt * 64 + sub + 4 * j;
            s[j] = (kg <= qglob) ? s[j] * 0.125f : -1e30f;
            tmax = fmaxf(tmax, s[j]);
        }
        tmax = fmaxf(tmax, __shfl_xor_sync(0xffffffff, tmax, 1));
        tmax = fmaxf(tmax, __shfl_xor_sync(0xffffffff, tmax, 2));
        float m_new = fmaxf(m_i, tmax);
        float scale = expf(m_i - m_new);
        float lsum = 0.f;
#pragma unroll
        for (int j = 0; j < 16; j++) {
            float p = expf(s[j] - m_new);
            Ps[q * APITCH + sub + 4 * j] = p;
            lsum += p;
        }
        lsum += __shfl_xor_sync(0xffffffff, lsum, 1);
        lsum += __shfl_xor_sync(0xffffffff, lsum, 2);
        l_i = l_i * scale + lsum;
        m_i = m_new;
        __syncwarp();
#pragma unroll
        for (int i = 0; i < 16; i++) acc[i] *= scale;
        for (int k = 0; k < 64; k++) {
            float p = Ps[q * APITCH + k];
#pragma unroll
            for (int c = 0; c < 4; c++) {
                float4 vv = *(const float4*)(Vs + k * APITCH + sub * 16 + c * 4);
                acc[c * 4 + 0] += p * vv.x; acc[c * 4 + 1] += p * vv.y;
                acc[c * 4 + 2] += p * vv.z; acc[c * 4 + 3] += p * vv.w;
            }
        }
    }
    float inv = 1.f / l_i;
    float* op = O + (size_t)(b * T_ + qglob) * D_ + h * HD_ + sub * 16;
#pragma unroll
    for (int c = 0; c < 4; c++)
        *(float4*)(op + c * 4) = make_float4(acc[c * 4] * inv, acc[c * 4 + 1] * inv,
                                             acc[c * 4 + 2] * inv, acc[c * 4 + 3] * inv);
}

// MoD attention: grid (B*H); Qc [BC][768]; KV [BT][1536]; Oc [BC][768]
__global__ __launch_bounds__(256) void fattn_mod_k(const float* __restrict__ Qc,
                                                   const float* __restrict__ KV,
                                                   const int* __restrict__ cidx,
                                                   float* __restrict__ Oc) {
    extern __shared__ float sm[];
    float* Qs = sm;
    float* Ks = sm + 64 * APITCH;
    float* Vs = sm + 2 * 64 * APITCH;
    float* Ps = sm + 3 * 64 * APITCH;
    int* qpos = (int*)(sm + 4 * 64 * APITCH);
    const int bh = blockIdx.x;
    const int b = bh / H_, h = bh % H_;
    const int tid = threadIdx.x;
    if (tid < 64) qpos[tid] = cidx[b * CAP_ + tid] - b * T_;
    for (int i = tid; i < 64 * 16; i += 256) {
        int r = i >> 4, c4 = i & 15;
        *(float4*)(Qs + r * APITCH + c4 * 4) =
            *(const float4*)(Qc + (size_t)(b * CAP_ + r) * D_ + h * HD_ + c4 * 4);
    }
    __syncthreads();
    const int ntiles = (qpos[63] >> 6) + 1;
    const int q = tid >> 2, sub = tid & 3;
    const int myqp = qpos[q];
    float m_i = -1e30f, l_i = 0.f;
    float acc[16];
#pragma unroll
    for (int i = 0; i < 16; i++) acc[i] = 0.f;

    for (int kt = 0; kt < ntiles; kt++) {
        __syncthreads();
        for (int i = tid; i < 64 * 16; i += 256) {
            int r = i >> 4, c4 = i & 15;
            const float* src = KV + (size_t)(b * T_ + kt * 64 + r) * (2 * D_) + h * HD_ + c4 * 4;
            *(float4*)(Ks + r * APITCH + c4 * 4) = *(const float4*)(src);
            *(float4*)(Vs + r * APITCH + c4 * 4) = *(const float4*)(src + D_);
        }
        __syncthreads();
        float s[16];
#pragma unroll
        for (int j = 0; j < 16; j++) s[j] = 0.f;
#pragma unroll 4
        for (int c4 = 0; c4 < 16; c4++) {
            float4 qv = *(const float4*)(Qs + q * APITCH + c4 * 4);
#pragma unroll
            for (int j = 0; j < 16; j++) {
                float4 kv = *(const float4*)(Ks + (sub + 4 * j) * APITCH + c4 * 4);
                s[j] += qv.x * kv.x + qv.y * kv.y + qv.z * kv.z + qv.w * kv.w;
            }
        }
        float tmax = -1e30f;
#pragma unroll
        for (int j = 0; j < 16; j++) {
            int kg = kt * 64 + sub + 4 * j;
            s[j] = (kg <= myqp) ? s[j] * 0.125f : -1e30f;
            tmax = fmaxf(tmax, s[j]);
        }
        tmax = fmaxf(tmax, __shfl_xor_sync(0xffffffff, tmax, 1));
        tmax = fmaxf(tmax, __shfl_xor_sync(0xffffffff, tmax, 2));
        float m_new = fmaxf(m_i, tmax);
        if (m_new == -1e30f) continue;  // no valid keys in this tile for this row
        float scale = expf(m_i - m_new);
        float lsum = 0.f;
#pragma unroll
        for (int j = 0; j < 16; j++) {
            float p = expf(s[j] - m_new);
            Ps[q * APITCH + sub + 4 * j] = p;
            lsum += p;
        }
        lsum += __shfl_xor_sync(0xffffffff, lsum, 1);
        lsum += __shfl_xor_sync(0xffffffff, lsum, 2);
        l_i = l_i * scale + lsum;
        m_i = m_new;
        __syncwarp();
#pragma unroll
        for (int i = 0; i < 16; i++) acc[i] *= scale;
        for (int k = 0; k < 64; k++) {
            float p = Ps[q * APITCH + k];
#pragma unroll
            for (int c = 0; c < 4; c++) {
                float4 vv = *(const float4*)(Vs + k * APITCH + sub * 16 + c * 4);
                acc[c * 4 + 0] += p * vv.x; acc[c * 4 + 1] += p * vv.y;
                acc[c * 4 + 2] += p * vv.z; acc[c * 4 + 3] += p * vv.w;
            }
        }
    }
    float inv = 1.f / l_i;
    float* op = Oc + (size_t)(b * CAP_ + q) * D_ + h * HD_ + sub * 16;
#pragma unroll
    for (int c = 0; c < 4; c++)
        *(float4*)(op + c * 4) = make_float4(acc[c * 4] * inv, acc[c * 4 + 1] * inv,
                                             acc[c * 4 + 2] * inv, acc[c * 4 + 3] * inv);
}

// ------------------- elementwise / small kernels -------------------
__global__ void embed_k(const int* __restrict__ ids, const float* __restrict__ E,
                        const float* __restrict__ Pw, float* __restrict__ X) {
    int m = blockIdx.x;
    int t = m % T_;
    int id = ids[m];
    for (int i = threadIdx.x; i < D_; i += 256)
        X[(size_t)m * D_ + i] = E[(size_t)id * D_ + i] + Pw[(size_t)t * D_ + i];
}

__global__ void rmsnorm_k(const float* __restrict__ X, const float* __restrict__ w,
                          float* __restrict__ Yb) {
    int m = blockIdx.x;
    const float* x = X + (size_t)m * D_;
    float s = 0.f;
    for (int i = threadIdx.x; i < D_; i += 256) { float v = x[i]; s += v * v; }
    __shared__ float red[256];
    red[threadIdx.x] = s; __syncthreads();
    for (int st = 128; st > 0; st >>= 1) {
        if (threadIdx.x < st) red[threadIdx.x] += red[threadIdx.x + st];
        __syncthreads();
    }
    float scale = rsqrtf(red[0] / (float)D_ + 1e-6f);
    for (int i = threadIdx.x; i < D_; i += 256)
        Yb[(size_t)m * D_ + i] = x[i] * scale * w[i];
}

__global__ void swiglu_k(float* __restrict__ U, const float* __restrict__ V, int n) {
    int i = blockIdx.x * blockDim.x + threadIdx.x;
    if (i < n) {
        float u = U[i];
        float s = u / (1.f + expf(-u));
        U[i] = s * V[i];
    }
}

__global__ void router_score_k(const float* __restrict__ X, const float* __restrict__ rw,
                               float* __restrict__ sc) {
    int m = blockIdx.x;
    float s = 0.f;
    for (int i = threadIdx.x; i < D_; i += 256) s += X[(size_t)m * D_ + i] * rw[i];
    __shared__ float red[256];
    red[threadIdx.x] = s; __syncthreads();
    for (int st = 128; st > 0; st >>= 1) {
        if (threadIdx.x < st) red[threadIdx.x] += red[threadIdx.x + st];
        __syncthreads();
    }
    if (threadIdx.x == 0) sc[m] = red[0];
}

// top-CAP selection + compact ascending index list
__global__ void topk_cidx_k(const float* __restrict__ sc, int* __restrict__ cidx) {
    int b = blockIdx.x, t = threadIdx.x;  // 512 threads
    __shared__ float s[T_];
    __shared__ int flag[T_];
    s[t] = sc[b * T_ + t];
    __syncthreads();
    float mine = s[t];
    int rank = 0;
    for (int j = 0; j < T_; j++) {
        float v = s[j];
        if (v > mine || (v == mine && j < t)) rank++;
    }
    int selected = (rank < CAP_) ? 1 : 0;
    flag[t] = selected;
    __syncthreads();
    if (selected) {
        int pos = 0;
        for (int j = 0; j < t; j++) pos += flag[j];
        cidx[b * CAP_ + pos] = b * T_ + t;
    }
}

__global__ void gather_k(const float* __restrict__ X, const int* __restrict__ cidx,
                         float* __restrict__ Yc) {
    int i = blockIdx.x;
    int row = cidx[i];
    for (int d = threadIdx.x; d < D_; d += 256)
        Yc[(size_t)i * D_ + d] = X[(size_t)row * D_ + d];
}

__global__ void scatter_k(const float* __restrict__ Yc, const int* __restrict__ cidx,
                          float* __restrict__ X) {
    int i = blockIdx.x;
    int row = cidx[i];
    for (int d = threadIdx.x; d < D_; d += 256)
        X[(size_t)row * D_ + d] = Yc[(size_t)i * D_ + d];
}

__global__ void memtopk_k(const float* __restrict__ SIM, const float* __restrict__ MV,
                          float* __restrict__ RETP) {
    int m = blockIdx.x;
    int tid = threadIdx.x;  // 256
    __shared__ float s[NMEM_];
    __shared__ float wts[TOPK_];
    __shared__ int idxs[TOPK_];
    __shared__ float rv[256];
    __shared__ int ri[256];
    const float invs = 0.03608439182435161f;  // 1/sqrt(768)
    for (int i = tid; i < NMEM_; i += 256) s[i] = SIM[(size_t)m * NMEM_ + i] * invs;
    __syncthreads();
    for (int j = 0; j < TOPK_; j++) {
        float bv = -1e30f; int bi = 0x7fffffff;
        for (int i = tid; i < NMEM_; i += 256) {
            if (s[i] > bv) { bv = s[i]; bi = i; }
        }
        rv[tid] = bv; ri[tid] = bi; __syncthreads();
        for (int st = 128; st > 0; st >>= 1) {
            if (tid < st) {
                if (rv[tid + st] > rv[tid] ||
                    (rv[tid + st] == rv[tid] && ri[tid + st] < ri[tid])) {
                    rv[tid] = rv[tid + st]; ri[tid] = ri[tid + st];
                }
            }
            __syncthreads();
        }
        if (tid == 0) { wts[j] = rv[0]; idxs[j] = ri[0]; s[ri[0]] = -1e30f; }
        __syncthreads();
    }
    if (tid == 0) {
        float mx = wts[0];
        float sum = 0.f;
        for (int j = 0; j < TOPK_; j++) { wts[j] = expf(wts[j] - mx); sum += wts[j]; }
        float inv = 1.f / sum;
        for (int j = 0; j < TOPK_; j++) wts[j] *= inv;
    }
    __syncthreads();
    for (int i = tid; i < D_; i += 256) {
        float a = 0.f;
#pragma unroll
        for (int j = 0; j < TOPK_; j++) a += wts[j] * MV[(size_t)idxs[j] * D_ + i];
        RETP[(size_t)m * D_ + i] = a;
    }
}

__global__ void concat_k(const float* __restrict__ X, const float* __restrict__ RET,
                         float* __restrict__ GI) {
    int m = blockIdx.x;
    for (int i = threadIdx.x; i < D_; i += 256) {
        GI[(size_t)m * 2 * D_ + i] = X[(size_t)m * D_ + i];
        GI[(size_t)m * 2 * D_ + D_ + i] = RET[(size_t)m * D_ + i];
    }
}

__global__ void gelu_bias_k(float* __restrict__ H1, const float* __restrict__ b1, int n) {
    int i = blockIdx.x * blockDim.x + threadIdx.x;
    if (i < n) {
        int col = i % (D_ / 2);
        float v = H1[i] + b1[col];
        H1[i] = 0.5f * v * (1.f + erff(v * 0.70710678118654752f));
    }
}

__global__ void gate_k(const float* __restrict__ H1, const float* __restrict__ w2,
                       const float* __restrict__ b2, const float* __restrict__ RET,
                       float* __restrict__ X) {
    int m = blockIdx.x;
    float s = 0.f;
    for (int i = threadIdx.x; i < D_ / 2; i += 256)
        s += H1[(size_t)m * (D_ / 2) + i] * w2[i];
    __shared__ float red[256];
    red[threadIdx.x] = s; __syncthreads();
    for (int st = 128; st > 0; st >>= 1) {
        if (threadIdx.x < st) red[threadIdx.x] += red[threadIdx.x + st];
        __syncthreads();
    }
    __shared__ float gsh;
    if (threadIdx.x == 0) gsh = 1.f / (1.f + expf(-(red[0] + b2[0])));
    __syncthreads();
    float g = gsh;
    for (int i = threadIdx.x; i < D_; i += 256)
        X[(size_t)m * D_ + i] += g * RET[(size_t)m * D_ + i];
}

// ------------------- host orchestration -------------------
static void gemm(const float* A, const float* Bw, float* C, int M, int N, int K, bool acc) {
    dim3 grid((N + 127) / 128, M / 128);
    if (N % 128 == 0) {
        if (acc) mmah_gemm_nt<true, false><<<grid, 256>>>(A, Bw, C, M, N, K);
        else     mmah_gemm_nt<false, false><<<grid, 256>>>(A, Bw, C, M, N, K);
    } else {
        if (acc) mmah_gemm_nt<true, true><<<grid, 256>>>(A, Bw, C, M, N, K);
        else     mmah_gemm_nt<false, true><<<grid, 256>>>(A, Bw, C, M, N, K);
    }
}

struct Ptrs {
    float *X, *Y, *Hb, *QKV, *ATT, *U, *V2, *SIM, *RETP, *RET, *GI, *H1, *SC;
    int* CIDX;
};

// full transformer block (non-MoD)
static void tblock_full(const Ptrs& p, const float* qkv_w, const float* out_w,
                        const float* n1, const float* n2, const float* w1,
                        const float* w2, const float* w3, float* x) {
    rmsnorm_k<<<BT_, 256>>>(x, n1, p.Hb);
    gemm(p.Hb, qkv_w, p.QKV, BT_, QKVD_, D_, false);
    fattn_k<<<dim3(T_ / 64, B_ * H_), 256, FA_SMEM>>>(p.QKV, p.ATT);
    gemm(p.ATT, out_w, x, BT_, D_, D_, true);
    rmsnorm_k<<<BT_, 256>>>(x, n2, p.Hb);
    gemm(p.Hb, w1, p.U, BT_, DFF_, D_, false);
    gemm(p.Hb, w2, p.V2, BT_, DFF_, D_, false);
    swiglu_k<<<(BT_ * DFF_ + 255) / 256, 256>>>(p.U, p.V2, BT_ * DFF_);
    gemm(p.U, w3, x, BT_, D_, DFF_, true);
}

// MoD block: compute on 256 selected rows only (K/V from all rows)
static void tblock_mod(const Ptrs& p, const float* qkv_w, const float* out_w,
                       const float* n1, const float* n2, const float* w1,
                       const float* w2, const float* w3, const float* rw) {
    float* KV = p.QKV;                                    // [BT][1536]
    float* Qc = p.QKV + (size_t)BT_ * (2 * D_);           // [BC][768]
    float* Xc = p.Y;                                      // [BC][768]
    float* Hc = p.RETP;                                   // [BC][768] (scratch)
    float* Oc = p.ATT;                                    // [BC][768]

    router_score_k<<<BT_, 256>>>(p.X, rw, p.SC);
    topk_cidx_k<<<B_, T_>>>(p.SC, p.CIDX);
    rmsnorm_k<<<BT_, 256>>>(p.X, n1, p.Hb);
    gemm(p.Hb, qkv_w + (size_t)D_ * D_, KV, BT_, 2 * D_, D_, false);  // K,V all rows
    gather_k<<<BC_, 256>>>(p.Hb, p.CIDX, Hc);
    gemm(Hc, qkv_w, Qc, BC_, D_, D_, false);                          // Q selected
    fattn_mod_k<<<B_ * H_, 256, FAM_SMEM>>>(Qc, KV, p.CIDX, Oc);
    gather_k<<<BC_, 256>>>(p.X, p.CIDX, Xc);
    gemm(Oc, out_w, Xc, BC_, D_, D_, true);
    rmsnorm_k<<<BC_, 256>>>(Xc, n2, Hc);
    gemm(Hc, w1, p.U, BC_, DFF_, D_, false);
    gemm(Hc, w2, p.V2, BC_, DFF_, D_, false);
    swiglu_k<<<(BC_ * DFF_ + 255) / 256, 256>>>(p.U, p.V2, BC_ * DFF_);
    gemm(p.U, w3, Xc, BC_, D_, DFF_, true);
    scatter_k<<<BC_, 256>>>(Xc, p.CIDX, p.X);
}

extern "C" void kernel_launch(void* const* d_in, const int* in_sizes, int n_in,
                              void* d_out, int out_size) {
    const int*   ids       = (const int*)d_in[0];
    const float* embed_w   = (const float*)d_in[1];
    const float* pos_w     = (const float*)d_in[2];
    const float* qkv_w     = (const float*)d_in[3];
    const float* out_w     = (const float*)d_in[4];
    const float* norm1_w   = (const float*)d_in[5];
    const float* norm2_w   = (const float*)d_in[6];
    const float* ff_w1     = (const float*)d_in[7];
    const float* ff_w2     = (const float*)d_in[8];
    const float* ff_w3     = (const float*)d_in[9];
    const float* router_w  = (const float*)d_in[10];
    const float* lat_qkv_w = (const float*)d_in[11];
    const float* lat_out_w = (const float*)d_in[12];
    const float* lat_n1    = (const float*)d_in[13];
    const float* lat_n2    = (const float*)d_in[14];
    const float* lat_w1    = (const float*)d_in[15];
    const float* lat_w2    = (const float*)d_in[16];
    const float* lat_w3    = (const float*)d_in[17];
    const float* mem_keys  = (const float*)d_in[18];
    const float* mem_values= (const float*)d_in[19];
    const float* mem_qp    = (const float*)d_in[20];
    const float* mem_op    = (const float*)d_in[21];
    const float* gate_w1   = (const float*)d_in[22];
    const float* gate_b1   = (const float*)d_in[23];
    const float* gate_w2   = (const float*)d_in[24];
    const float* gate_b2   = (const float*)d_in[25];
    const float* final_nw  = (const float*)d_in[26];
    float* out = (float*)d_out;

    static bool attr_done = false;
    if (!attr_done) {
        cudaFuncSetAttribute(fattn_k, cudaFuncAttributeMaxDynamicSharedMemorySize, FA_SMEM);
        cudaFuncSetAttribute(fattn_mod_k, cudaFuncAttributeMaxDynamicSharedMemorySize, FAM_SMEM);
        attr_done = true;
    }

    Ptrs p;
    cudaGetSymbolAddress((void**)&p.X, g_X);
    cudaGetSymbolAddress((void**)&p.Y, g_Y);
    cudaGetSymbolAddress((void**)&p.Hb, g_Hb);
    cudaGetSymbolAddress((void**)&p.QKV, g_QKV);
    cudaGetSymbolAddress((void**)&p.ATT, g_ATT);
    cudaGetSymbolAddress((void**)&p.U, g_U);
    cudaGetSymbolAddress((void**)&p.V2, g_V2);
    cudaGetSymbolAddress((void**)&p.SIM, g_SIM);
    cudaGetSymbolAddress((void**)&p.RETP, g_RETP);
    cudaGetSymbolAddress((void**)&p.RET, g_RET);
    cudaGetSymbolAddress((void**)&p.GI, g_GI);
    cudaGetSymbolAddress((void**)&p.H1, g_H1);
    cudaGetSymbolAddress((void**)&p.SC, g_SC);
    cudaGetSymbolAddress((void**)&p.CIDX, g_CIDX);

    embed_k<<<BT_, 256>>>(ids, embed_w, pos_w, p.X);

    for (int i = 0; i < L_; i++) {
        const float* qw = qkv_w + (size_t)i * QKVD_ * D_;
        const float* ow = out_w + (size_t)i * D_ * D_;
        const float* n1 = norm1_w + (size_t)i * D_;
        const float* n2 = norm2_w + (size_t)i * D_;
        const float* w1 = ff_w1 + (size_t)i * DFF_ * D_;
        const float* w2 = ff_w2 + (size_t)i * DFF_ * D_;
        const float* w3 = ff_w3 + (size_t)i * D_ * DFF_;
        if (i % 2 == 1)
            tblock_mod(p, qw, ow, n1, n2, w1, w2, w3, router_w + (size_t)i * D_);
        else
            tblock_full(p, qw, ow, n1, n2, w1, w2, w3, p.X);
    }

    for (int it = 0; it < NLAT_; it++)
        tblock_full(p, lat_qkv_w, lat_out_w, lat_n1, lat_n2, lat_w1, lat_w2, lat_w3, p.X);

    // kNN memory retrieval
    gemm(p.X, mem_qp, p.Hb, BT_, D_, D_, false);          // q
    gemm(p.Hb, mem_keys, p.SIM, BT_, NMEM_, D_, false);   // sim (unscaled)
    memtopk_k<<<BT_, 256>>>(p.SIM, mem_values, p.RETP);
    gemm(p.RETP, mem_op, p.RET, BT_, D_, D_, false);
    concat_k<<<BT_, 256>>>(p.X, p.RET, p.GI);
    gemm(p.GI, gate_w1, p.H1, BT_, D_ / 2, 2 * D_, false);
    gelu_bias_k<<<(BT_ * (D_ / 2) + 255) / 256, 256>>>(p.H1, gate_b1, BT_ * (D_ / 2));
    gate_k<<<BT_, 256>>>(p.H1, gate_w2, gate_b2, p.RET, p.X);

    // final norm + tied LM head
    rmsnorm_k<<<BT_, 256>>>(p.X, final_nw, p.Hb);
    gemm(p.Hb, embed_w, out, BT_, VOCAB_, D_, false);
}

// round 13
// speedup vs baseline: 3.9272x; 1.0653x over previous
#include <cuda_runtime.h>
#include <cuda_bf16.h>
#include <cuda_fp16.h>
#include <math.h>
#include <stdint.h>

#define B_ 4
#define T_ 512
#define D_ 768
#define H_ 12
#define HD_ 64
#define L_ 12
#define DFF_ 2048
#define VOCAB_ 50257
#define NMEM_ 1024
#define TOPK_ 8
#define NLAT_ 4
#define CAP_ 64
#define BT_ (B_*T_)
#define QKVD_ (3*D_)
#define BC_ (B_*CAP_)   // 256 compacted rows

// ------------------- scratch (device globals; no allocation) -------------------
__device__ float g_X[BT_*D_];
__device__ float g_Y[BT_*D_];
__device__ float g_Hb[BT_*D_];
__device__ float g_QKV[BT_*QKVD_];
__device__ float g_ATT[BT_*D_];
__device__ float g_U[BT_*DFF_];
__device__ float g_V2[BT_*DFF_];
__device__ float g_SIM[BT_*NMEM_];
__device__ float g_RETP[BT_*D_];
__device__ float g_RET[BT_*D_];
__device__ float g_GI[BT_*2*D_];
__device__ float g_H1[BT_*(D_/2)];
__device__ float g_SC[BT_];
__device__ int   g_CIDX[BT_];

// ==================== 3x-split FP16 mma.sync GEMM (m16n8k16) ====================
#define PITCH2 12
#define TILE_U (128 * PITCH2)

__device__ __forceinline__ uint32_t pkh(__half a, __half b) {
    __half2 h = __halves2half2(a, b);
    return *(uint32_t*)&h;
}

__device__ __forceinline__ void mma_f16(float* c, uint32_t a0, uint32_t a1,
                                        uint32_t a2, uint32_t a3,
                                        uint32_t b0, uint32_t b1) {
    asm volatile(
        "mma.sync.aligned.m16n8k16.row.col.f32.f16.f16.f32 "
        "{%0,%1,%2,%3}, {%4,%5,%6,%7}, {%8,%9}, {%0,%1,%2,%3};"
        : "+f"(c[0]), "+f"(c[1]), "+f"(c[2]), "+f"(c[3])
        : "r"(a0), "r"(a1), "r"(a2), "r"(a3), "r"(b0), "r"(b1));
}

template<bool ACC, bool NGUARD>
__global__ __launch_bounds__(256, 2) void mmah_gemm_nt(const float* __restrict__ A,
                                                       const float* __restrict__ Bw,
                                                       float* __restrict__ C,
                                                       int M, int N, int K) {
    __shared__ uint32_t smu[2 * 4 * TILE_U];
    const int bm = blockIdx.y * 128, bn = blockIdx.x * 128;
    const int tid = threadIdx.x;
    const int wid = tid >> 5, lane = tid & 31;
    const int warp_m = wid >> 2, warp_n = wid & 3;
    const int g = lane >> 2, tg = lane & 3;

    float acc[4][4][4];
#pragma unroll
    for (int mi = 0; mi < 4; mi++)
#pragma unroll
        for (int ni = 0; ni < 4; ni++)
#pragma unroll
            for (int e = 0; e < 4; e++) acc[mi][ni][e] = 0.f;

    const int r_0 = tid >> 2,         c4_0 = (tid & 3);
    const int r_1 = (tid + 256) >> 2, c4_1 = ((tid + 256) & 3);
    const float* a0p = A + (size_t)(bm + r_0) * K + c4_0 * 4;
    const float* a1p = A + (size_t)(bm + r_1) * K + c4_1 * 4;
    const bool b0ok = !NGUARD || (bn + r_0) < N;
    const bool b1ok = !NGUARD || (bn + r_1) < N;
    const float* b0p = Bw + (size_t)(bn + r_0) * K + c4_0 * 4;
    const float* b1p = Bw + (size_t)(bn + r_1) * K + c4_1 * 4;

    const int nt = K >> 4;
    float4 ra0, ra1, rb0, rb1;

    ra0 = *(const float4*)(a0p);
    ra1 = *(const float4*)(a1p);
    rb0 = b0ok ? *(const float4*)(b0p) : make_float4(0.f, 0.f, 0.f, 0.f);
    rb1 = b1ok ? *(const float4*)(b1p) : make_float4(0.f, 0.f, 0.f, 0.f);

    for (int t = 0; t < nt; t++) {
        const int s = t & 1;
        uint32_t* st = smu + s * 4 * TILE_U;
        {
            auto put = [&](uint32_t* tH, uint32_t* tL, int r, int c4, float4 v) {
                __half hx = __float2half_rn(v.x), hy = __float2half_rn(v.y);
                __half hz = __float2half_rn(v.z), hw = __float2half_rn(v.w);
                uint32_t h0 = pkh(hx, hy), h1 = pkh(hz, hw);
                uint32_t l0 = pkh(__float2half_rn(v.x - __half2float(hx)),
                                  __float2half_rn(v.y - __half2float(hy)));
                uint32_t l1 = pkh(__float2half_rn(v.z - __half2float(hz)),
                                  __float2half_rn(v.w - __half2float(hw)));
                int idx = r * PITCH2 + c4 * 2;
                *(uint2*)&tH[idx] = make_uint2(h0, h1);
                *(uint2*)&tL[idx] = make_uint2(l0, l1);
            };
            put(st,              st + TILE_U,     r_0, c4_0, ra0);
            put(st,              st + TILE_U,     r_1, c4_1, ra1);
            put(st + 2 * TILE_U, st + 3 * TILE_U, r_0, c4_0, rb0);
            put(st + 2 * TILE_U, st + 3 * TILE_U, r_1, c4_1, rb1);
        }
        if (t + 1 < nt) {
            const int k0 = (t + 1) << 4;
            ra0 = *(const float4*)(a0p + k0);
            ra1 = *(const float4*)(a1p + k0);
            rb0 = b0ok ? *(const float4*)(b0p + k0) : make_float4(0.f, 0.f, 0.f, 0.f);
            rb1 = b1ok ? *(const float4*)(b1p + k0) : make_float4(0.f, 0.f, 0.f, 0.f);
        }
        __syncthreads();

        const uint32_t* Ah = smu + s * 4 * TILE_U;
        const uint32_t* Al = Ah + TILE_U;
        const uint32_t* Bh = Ah + 2 * TILE_U;
        const uint32_t* Bl = Ah + 3 * TILE_U;

        uint32_t bh[4][2], bl[4][2];
#pragma unroll
        for (int ni = 0; ni < 4; ni++) {
            const int rb = (warp_n * 32 + ni * 8 + g) * PITCH2 + tg;
            bh[ni][0] = Bh[rb]; bh[ni][1] = Bh[rb + 4];
            bl[ni][0] = Bl[rb]; bl[ni][1] = Bl[rb + 4];
        }
#pragma unroll
        for (int mi = 0; mi < 4; mi++) {
            const int ra = (warp_m * 64 + mi * 16 + g) * PITCH2 + tg;
            const uint32_t ah0 = Ah[ra], ah1 = Ah[ra + 8 * PITCH2];
            const uint32_t ah2 = Ah[ra + 4], ah3 = Ah[ra + 8 * PITCH2 + 4];
            const uint32_t al0 = Al[ra], al1 = Al[ra + 8 * PITCH2];
            const uint32_t al2 = Al[ra + 4], al3 = Al[ra + 8 * PITCH2 + 4];
#pragma unroll
            for (int ni = 0; ni < 4; ni++) {
                mma_f16(acc[mi][ni], al0, al1, al2, al3, bh[ni][0], bh[ni][1]);
                mma_f16(acc[mi][ni], ah0, ah1, ah2, ah3, bl[ni][0], bl[ni][1]);
                mma_f16(acc[mi][ni], ah0, ah1, ah2, ah3, bh[ni][0], bh[ni][1]);
            }
        }
    }

#pragma unroll
    for (int mi = 0; mi < 4; mi++) {
#pragma unroll
        for (int ni = 0; ni < 4; ni++) {
            int row0 = bm + warp_m * 64 + mi * 16 + g;
            int col = bn + warp_n * 32 + ni * 8 + tg * 2;
#pragma unroll
            for (int rr = 0; rr < 2; rr++) {
                int row = row0 + rr * 8;
                float* cp = C + (size_t)row * N + col;
                float v0 = acc[mi][ni][rr * 2 + 0];
                float v1 = acc[mi][ni][rr * 2 + 1];
                if (!NGUARD || col + 1 < N) {
                    if (ACC) { cp[0] += v0; cp[1] += v1; }
                    else     { cp[0] = v0;  cp[1] = v1; }
                } else if (col < N) {
                    if (ACC) cp[0] += v0; else cp[0] = v0;
                }
            }
        }
    }
}

// ==================== fused flash-style attention ====================
// 256 threads: thread -> (q = tid>>2, sub = tid&3). Online softmax.
// K/V tiles: register prefetch of tile t+1 overlaps compute of tile t.
#define APITCH 68
#define FA_SMEM (4 * 64 * APITCH * 4)
#define FAM_SMEM (FA_SMEM + 64 * 4)

// Full attention: grid (T/64, B*H); QKV [BT][2304]; O [BT][768]
__global__ __launch_bounds__(256) void fattn_k(const float* __restrict__ QKV,
                                               float* __restrict__ O) {
    extern __shared__ float sm[];
    float* Qs = sm;
    float* Ks = sm + 64 * APITCH;
    float* Vs = sm + 2 * 64 * APITCH;
    float* Ps = sm + 3 * 64 * APITCH;
    const int qt = gridDim.x - 1 - blockIdx.x;  // long blocks first
    const int bh = blockIdx.y;
    const int b = bh / H_, h = bh % H_;
    const int tid = threadIdx.x;
    const int q0 = qt * 64;
    // Q tile -> smem
    for (int i = tid; i < 64 * 16; i += 256) {
        int r = i >> 4, c4 = i & 15;
        *(float4*)(Qs + r * APITCH + c4 * 4) =
            *(const float4*)(QKV + (size_t)(b * T_ + q0 + r) * QKVD_ + h * HD_ + c4 * 4);
    }
    const int q = tid >> 2, sub = tid & 3;
    const int qglob = q0 + q;
    // K/V stage coordinates: 4 float4 each per thread
    int rr_[4], cc_[4];
#pragma unroll
    for (int j = 0; j < 4; j++) { int i = tid + 256 * j; rr_[j] = i >> 4; cc_[j] = i & 15; }
    float4 kreg[4], vreg[4];
    {
#pragma unroll
        for (int j = 0; j < 4; j++) {
            const float* src = QKV + (size_t)(b * T_ + rr_[j]) * QKVD_ + h * HD_ + cc_[j] * 4;
            kreg[j] = *(const float4*)(src + D_);
            vreg[j] = *(const float4*)(src + 2 * D_);
        }
    }
    float m_i = -1e30f, l_i = 0.f;
    float acc[16];
#pragma unroll
    for (int i = 0; i < 16; i++) acc[i] = 0.f;

    for (int kt = 0; kt <= qt; kt++) {
        __syncthreads();  // prior compute done reading Ks/Vs
#pragma unroll
        for (int j = 0; j < 4; j++) {
            *(float4*)(Ks + rr_[j] * APITCH + cc_[j] * 4) = kreg[j];
            *(float4*)(Vs + rr_[j] * APITCH + cc_[j] * 4) = vreg[j];
        }
        __syncthreads();
        if (kt < qt) {  // prefetch next tile (overlaps compute)
#pragma unroll
            for (int j = 0; j < 4; j++) {
                const float* src = QKV + (size_t)(b * T_ + (kt + 1) * 64 + rr_[j]) * QKVD_
                                   + h * HD_ + cc_[j] * 4;
                kreg[j] = *(const float4*)(src + D_);
                vreg[j] = *(const float4*)(src + 2 * D_);
            }
        }
        float s[16];
#pragma unroll
        for (int j = 0; j < 16; j++) s[j] = 0.f;
#pragma unroll 4
        for (int c4 = 0; c4 < 16; c4++) {
            float4 qv = *(const float4*)(Qs + q * APITCH + c4 * 4);
#pragma unroll
            for (int j = 0; j < 16; j++) {
                float4 kv = *(const float4*)(Ks + (sub + 4 * j) * APITCH + c4 * 4);
                s[j] += qv.x * kv.x + qv.y * kv.y + qv.z * kv.z + qv.w * kv.w;
            }
        }
        float tmax = -1e30f;
#pragma unroll
        for (int j = 0; j < 16; j++) {
            int kg = kt * 64 + sub + 4 * j;
            s[j] = (kg <= qglob) ? s[j] * 0.125f : -1e30f;
            tmax = fmaxf(tmax, s[j]);
        }
        tmax = fmaxf(tmax, __shfl_xor_sync(0xffffffff, tmax, 1));
        tmax = fmaxf(tmax, __shfl_xor_sync(0xffffffff, tmax, 2));
        float m_new = fmaxf(m_i, tmax);
        float scale = expf(m_i - m_new);
        float lsum = 0.f;
#pragma unroll
        for (int j = 0; j < 16; j++) {
            float p = expf(s[j] - m_new);
            Ps[q * APITCH + sub + 4 * j] = p;
            lsum += p;
        }
        lsum += __shfl_xor_sync(0xffffffff, lsum, 1);
        lsum += __shfl_xor_sync(0xffffffff, lsum, 2);
        l_i = l_i * scale + lsum;
        m_i = m_new;
        __syncwarp();
#pragma unroll
        for (int i = 0; i < 16; i++) acc[i] *= scale;
#pragma unroll 2
        for (int k4 = 0; k4 < 64; k4 += 4) {
            float4 pv = *(const float4*)(Ps + q * APITCH + k4);
            float pa[4] = {pv.x, pv.y, pv.z, pv.w};
#pragma unroll
            for (int kk = 0; kk < 4; kk++) {
                float p = pa[kk];
#pragma unroll
                for (int c = 0; c < 4; c++) {
                    float4 vv = *(const float4*)(Vs + (k4 + kk) * APITCH + sub * 16 + c * 4);
                    acc[c * 4 + 0] += p * vv.x; acc[c * 4 + 1] += p * vv.y;
                    acc[c * 4 + 2] += p * vv.z; acc[c * 4 + 3] += p * vv.w;
                }
            }
        }
    }
    float inv = 1.f / l_i;
    float* op = O + (size_t)(b * T_ + qglob) * D_ + h * HD_ + sub * 16;
#pragma unroll
    for (int c = 0; c < 4; c++)
        *(float4*)(op + c * 4) = make_float4(acc[c * 4] * inv, acc[c * 4 + 1] * inv,
                                             acc[c * 4 + 2] * inv, acc[c * 4 + 3] * inv);
}

// MoD attention: grid (B*H); Qc [BC][768]; KV [BT][1536]; Oc [BC][768]
__global__ __launch_bounds__(256) void fattn_mod_k(const float* __restrict__ Qc,
                                                   const float* __restrict__ KV,
                                                   const int* __restrict__ cidx,
                                                   float* __restrict__ Oc) {
    extern __shared__ float sm[];
    float* Qs = sm;
    float* Ks = sm + 64 * APITCH;
    float* Vs = sm + 2 * 64 * APITCH;
    float* Ps = sm + 3 * 64 * APITCH;
    int* qpos = (int*)(sm + 4 * 64 * APITCH);
    const int bh = blockIdx.x;
    const int b = bh / H_, h = bh % H_;
    const int tid = threadIdx.x;
    if (tid < 64) qpos[tid] = cidx[b * CAP_ + tid] - b * T_;
    for (int i = tid; i < 64 * 16; i += 256) {
        int r = i >> 4, c4 = i & 15;
        *(float4*)(Qs + r * APITCH + c4 * 4) =
            *(const float4*)(Qc + (size_t)(b * CAP_ + r) * D_ + h * HD_ + c4 * 4);
    }
    __syncthreads();
    const int ntiles = (qpos[63] >> 6) + 1;
    const int q = tid >> 2, sub = tid & 3;
    const int myqp = qpos[q];
    int rr_[4], cc_[4];
#pragma unroll
    for (int j = 0; j < 4; j++) { int i = tid + 256 * j; rr_[j] = i >> 4; cc_[j] = i & 15; }
    float4 kreg[4], vreg[4];
#pragma unroll
    for (int j = 0; j < 4; j++) {
        const float* src = KV + (size_t)(b * T_ + rr_[j]) * (2 * D_) + h * HD_ + cc_[j] * 4;
        kreg[j] = *(const float4*)(src);
        vreg[j] = *(const float4*)(src + D_);
    }
    float m_i = -1e30f, l_i = 0.f;
    float acc[16];
#pragma unroll
    for (int i = 0; i < 16; i++) acc[i] = 0.f;

    for (int kt = 0; kt < ntiles; kt++) {
        __syncthreads();
#pragma unroll
        for (int j = 0; j < 4; j++) {
            *(float4*)(Ks + rr_[j] * APITCH + cc_[j] * 4) = kreg[j];
            *(float4*)(Vs + rr_[j] * APITCH + cc_[j] * 4) = vreg[j];
        }
        __syncthreads();
        if (kt + 1 < ntiles) {
#pragma unroll
            for (int j = 0; j < 4; j++) {
                const float* src = KV + (size_t)(b * T_ + (kt + 1) * 64 + rr_[j]) * (2 * D_)
                                   + h * HD_ + cc_[j] * 4;
                kreg[j] = *(const float4*)(src);
                vreg[j] = *(const float4*)(src + D_);
            }
        }
        float s[16];
#pragma unroll
        for (int j = 0; j < 16; j++) s[j] = 0.f;
#pragma unroll 4
        for (int c4 = 0; c4 < 16; c4++) {
            float4 qv = *(const float4*)(Qs + q * APITCH + c4 * 4);
#pragma unroll
            for (int j = 0; j < 16; j++) {
                float4 kv = *(const float4*)(Ks + (sub + 4 * j) * APITCH + c4 * 4);
                s[j] += qv.x * kv.x + qv.y * kv.y + qv.z * kv.z + qv.w * kv.w;
            }
        }
        float tmax = -1e30f;
#pragma unroll
        for (int j = 0; j < 16; j++) {
            int kg = kt * 64 + sub + 4 * j;
            s[j] = (kg <= myqp) ? s[j] * 0.125f : -1e30f;
            tmax = fmaxf(tmax, s[j]);
        }
        tmax = fmaxf(tmax, __shfl_xor_sync(0xffffffff, tmax, 1));
        tmax = fmaxf(tmax, __shfl_xor_sync(0xffffffff, tmax, 2));
        float m_new = fmaxf(m_i, tmax);
        if (m_new > -1e30f) {
            float scale = expf(m_i - m_new);
            float lsum = 0.f;
#pragma unroll
            for (int j = 0; j < 16; j++) {
                float p = expf(s[j] - m_new);
                Ps[q * APITCH + sub + 4 * j] = p;
                lsum += p;
            }
            lsum += __shfl_xor_sync(0xffffffff, lsum, 1);
            lsum += __shfl_xor_sync(0xffffffff, lsum, 2);
            l_i = l_i * scale + lsum;
            m_i = m_new;
            __syncwarp();
#pragma unroll
            for (int i = 0; i < 16; i++) acc[i] *= scale;
#pragma unroll 2
            for (int k4 = 0; k4 < 64; k4 += 4) {
                float4 pv = *(const float4*)(Ps + q * APITCH + k4);
                float pa[4] = {pv.x, pv.y, pv.z, pv.w};
#pragma unroll
                for (int kk = 0; kk < 4; kk++) {
                    float p = pa[kk];
#pragma unroll
                    for (int c = 0; c < 4; c++) {
                        float4 vv = *(const float4*)(Vs + (k4 + kk) * APITCH + sub * 16 + c * 4);
                        acc[c * 4 + 0] += p * vv.x; acc[c * 4 + 1] += p * vv.y;
                        acc[c * 4 + 2] += p * vv.z; acc[c * 4 + 3] += p * vv.w;
                    }
                }
            }
        }
    }
    float inv = 1.f / l_i;
    float* op = Oc + (size_t)(b * CAP_ + q) * D_ + h * HD_ + sub * 16;
#pragma unroll
    for (int c = 0; c < 4; c++)
        *(float4*)(op + c * 4) = make_float4(acc[c * 4] * inv, acc[c * 4 + 1] * inv,
                                             acc[c * 4 + 2] * inv, acc[c * 4 + 3] * inv);
}

// ------------------- elementwise / small kernels -------------------
__global__ void embed_k(const int* __restrict__ ids, const float* __restrict__ E,
                        const float* __restrict__ Pw, float* __restrict__ X) {
    int m = blockIdx.x;
    int t = m % T_;
    int id = ids[m];
    for (int i = threadIdx.x; i < D_; i += 256)
        X[(size_t)m * D_ + i] = E[(size_t)id * D_ + i] + Pw[(size_t)t * D_ + i];
}

__global__ void rmsnorm_k(const float* __restrict__ X, const float* __restrict__ w,
                          float* __restrict__ Yb) {
    int m = blockIdx.x;
    const float* x = X + (size_t)m * D_;
    float s = 0.f;
    for (int i = threadIdx.x; i < D_; i += 256) { float v = x[i]; s += v * v; }
    __shared__ float red[256];
    red[threadIdx.x] = s; __syncthreads();
    for (int st = 128; st > 0; st >>= 1) {
        if (threadIdx.x < st) red[threadIdx.x] += red[threadIdx.x + st];
        __syncthreads();
    }
    float scale = rsqrtf(red[0] / (float)D_ + 1e-6f);
    for (int i = threadIdx.x; i < D_; i += 256)
        Yb[(size_t)m * D_ + i] = x[i] * scale * w[i];
}

__global__ void swiglu_k(float* __restrict__ U, const float* __restrict__ V, int n) {
    int i = blockIdx.x * blockDim.x + threadIdx.x;
    if (i < n) {
        float u = U[i];
        float s = u / (1.f + expf(-u));
        U[i] = s * V[i];
    }
}

__global__ void router_score_k(const float* __restrict__ X, const float* __restrict__ rw,
                               float* __restrict__ sc) {
    int m = blockIdx.x;
    float s = 0.f;
    for (int i = threadIdx.x; i < D_; i += 256) s += X[(size_t)m * D_ + i] * rw[i];
    __shared__ float red[256];
    red[threadIdx.x] = s; __syncthreads();
    for (int st = 128; st > 0; st >>= 1) {
        if (threadIdx.x < st) red[threadIdx.x] += red[threadIdx.x + st];
        __syncthreads();
    }
    if (threadIdx.x == 0) sc[m] = red[0];
}

// top-CAP selection + compact ascending index list
__global__ void topk_cidx_k(const float* __restrict__ sc, int* __restrict__ cidx) {
    int b = blockIdx.x, t = threadIdx.x;  // 512 threads
    __shared__ float s[T_];
    __shared__ int flag[T_];
    s[t] = sc[b * T_ + t];
    __syncthreads();
    float mine = s[t];
    int rank = 0;
    for (int j = 0; j < T_; j++) {
        float v = s[j];
        if (v > mine || (v == mine && j < t)) rank++;
    }
    int selected = (rank < CAP_) ? 1 : 0;
    flag[t] = selected;
    __syncthreads();
    if (selected) {
        int pos = 0;
        for (int j = 0; j < t; j++) pos += flag[j];
        cidx[b * CAP_ + pos] = b * T_ + t;
    }
}

__global__ void gather_k(const float* __restrict__ X, const int* __restrict__ cidx,
                         float* __restrict__ Yc) {
    int i = blockIdx.x;
    int row = cidx[i];
    for (int d = threadIdx.x; d < D_; d += 256)
        Yc[(size_t)i * D_ + d] = X[(size_t)row * D_ + d];
}

__global__ void scatter_k(const float* __restrict__ Yc, const int* __restrict__ cidx,
                          float* __restrict__ X) {
    int i = blockIdx.x;
    int row = cidx[i];
    for (int d = threadIdx.x; d < D_; d += 256)
        X[(size_t)row * D_ + d] = Yc[(size_t)i * D_ + d];
}

__global__ void memtopk_k(const float* __restrict__ SIM, const float* __restrict__ MV,
                          float* __restrict__ RETP) {
    int m = blockIdx.x;
    int tid = threadIdx.x;  // 256
    __shared__ float s[NMEM_];
    __shared__ float wts[TOPK_];
    __shared__ int idxs[TOPK_];
    __shared__ float rv[256];
    __shared__ int ri[256];
    const float invs = 0.03608439182435161f;  // 1/sqrt(768)
    for (int i = tid; i < NMEM_; i += 256) s[i] = SIM[(size_t)m * NMEM_ + i] * invs;
    __syncthreads();
    for (int j = 0; j < TOPK_; j++) {
        float bv = -1e30f; int bi = 0x7fffffff;
        for (int i = tid; i < NMEM_; i += 256) {
            if (s[i] > bv) { bv = s[i]; bi = i; }
        }
        rv[tid] = bv; ri[tid] = bi; __syncthreads();
        for (int st = 128; st > 0; st >>= 1) {
            if (tid < st) {
                if (rv[tid + st] > rv[tid] ||
                    (rv[tid + st] == rv[tid] && ri[tid + st] < ri[tid])) {
                    rv[tid] = rv[tid + st]; ri[tid] = ri[tid + st];
                }
            }
            __syncthreads();
        }
        if (tid == 0) { wts[j] = rv[0]; idxs[j] = ri[0]; s[ri[0]] = -1e30f; }
        __syncthreads();
    }
    if (tid == 0) {
        float mx = wts[0];
        float sum = 0.f;
        for (int j = 0; j < TOPK_; j++) { wts[j] = expf(wts[j] - mx); sum += wts[j]; }
        float inv = 1.f / sum;
        for (int j = 0; j < TOPK_; j++) wts[j] *= inv;
    }
    __syncthreads();
    for (int i = tid; i < D_; i += 256) {
        float a = 0.f;
#pragma unroll
        for (int j = 0; j < TOPK_; j++) a += wts[j] * MV[(size_t)idxs[j] * D_ + i];
        RETP[(size_t)m * D_ + i] = a;
    }
}

__global__ void concat_k(const float* __restrict__ X, const float* __restrict__ RET,
                         float* __restrict__ GI) {
    int m = blockIdx.x;
    for (int i = threadIdx.x; i < D_; i += 256) {
        GI[(size_t)m * 2 * D_ + i] = X[(size_t)m * D_ + i];
        GI[(size_t)m * 2 * D_ + D_ + i] = RET[(size_t)m * D_ + i];
    }
}

__global__ void gelu_bias_k(float* __restrict__ H1, const float* __restrict__ b1, int n) {
    int i = blockIdx.x * blockDim.x + threadIdx.x;
    if (i < n) {
        int col = i % (D_ / 2);
        float v = H1[i] + b1[col];
        H1[i] = 0.5f * v * (1.f + erff(v * 0.70710678118654752f));
    }
}

__global__ void gate_k(const float* __restrict__ H1, const float* __restrict__ w2,
                       const float* __restrict__ b2, const float* __restrict__ RET,
                       float* __restrict__ X) {
    int m = blockIdx.x;
    float s = 0.f;
    for (int i = threadIdx.x; i < D_ / 2; i += 256)
        s += H1[(size_t)m * (D_ / 2) + i] * w2[i];
    __shared__ float red[256];
    red[threadIdx.x] = s; __syncthreads();
    for (int st = 128; st > 0; st >>= 1) {
        if (threadIdx.x < st) red[threadIdx.x] += red[threadIdx.x + st];
        __syncthreads();
    }
    __shared__ float gsh;
    if (threadIdx.x == 0) gsh = 1.f / (1.f + expf(-(red[0] + b2[0])));
    __syncthreads();
    float g = gsh;
    for (int i = threadIdx.x; i < D_; i += 256)
        X[(size_t)m * D_ + i] += g * RET[(size_t)m * D_ + i];
}

// ------------------- host orchestration -------------------
static void gemm(const float* A, const float* Bw, float* C, int M, int N, int K, bool acc) {
    dim3 grid((N + 127) / 128, M / 128);
    if (N % 128 == 0) {
        if (acc) mmah_gemm_nt<true, false><<<grid, 256>>>(A, Bw, C, M, N, K);
        else     mmah_gemm_nt<false, false><<<grid, 256>>>(A, Bw, C, M, N, K);
    } else {
        if (acc) mmah_gemm_nt<true, true><<<grid, 256>>>(A, Bw, C, M, N, K);
        else     mmah_gemm_nt<false, true><<<grid, 256>>>(A, Bw, C, M, N, K);
    }
}

struct Ptrs {
    float *X, *Y, *Hb, *QKV, *ATT, *U, *V2, *SIM, *RETP, *RET, *GI, *H1, *SC;
    int* CIDX;
};

// full transformer block (non-MoD)
static void tblock_full(const Ptrs& p, const float* qkv_w, const float* out_w,
                        const float* n1, const float* n2, const float* w1,
                        const float* w2, const float* w3, float* x) {
    rmsnorm_k<<<BT_, 256>>>(x, n1, p.Hb);
    gemm(p.Hb, qkv_w, p.QKV, BT_, QKVD_, D_, false);
    fattn_k<<<dim3(T_ / 64, B_ * H_), 256, FA_SMEM>>>(p.QKV, p.ATT);
    gemm(p.ATT, out_w, x, BT_, D_, D_, true);
    rmsnorm_k<<<BT_, 256>>>(x, n2, p.Hb);
    gemm(p.Hb, w1, p.U, BT_, DFF_, D_, false);
    gemm(p.Hb, w2, p.V2, BT_, DFF_, D_, false);
    swiglu_k<<<(BT_ * DFF_ + 255) / 256, 256>>>(p.U, p.V2, BT_ * DFF_);
    gemm(p.U, w3, x, BT_, D_, DFF_, true);
}

// MoD block: compute on 256 selected rows only (K/V from all rows)
static void tblock_mod(const Ptrs& p, const float* qkv_w, const float* out_w,
                       const float* n1, const float* n2, const float* w1,
                       const float* w2, const float* w3, const float* rw) {
    float* KV = p.QKV;                                    // [BT][1536]
    float* Qc = p.QKV + (size_t)BT_ * (2 * D_);           // [BC][768]
    float* Xc = p.Y;                                      // [BC][768]
    float* Hc = p.RETP;                                   // [BC][768] (scratch)
    float* Oc = p.ATT;                                    // [BC][768]

    router_score_k<<<BT_, 256>>>(p.X, rw, p.SC);
    topk_cidx_k<<<B_, T_>>>(p.SC, p.CIDX);
    rmsnorm_k<<<BT_, 256>>>(p.X, n1, p.Hb);
    gemm(p.Hb, qkv_w + (size_t)D_ * D_, KV, BT_, 2 * D_, D_, false);  // K,V all rows
    gather_k<<<BC_, 256>>>(p.Hb, p.CIDX, Hc);
    gemm(Hc, qkv_w, Qc, BC_, D_, D_, false);                          // Q selected
    fattn_mod_k<<<B_ * H_, 256, FAM_SMEM>>>(Qc, KV, p.CIDX, Oc);
    gather_k<<<BC_, 256>>>(p.X, p.CIDX, Xc);
    gemm(Oc, out_w, Xc, BC_, D_, D_, true);
    rmsnorm_k<<<BC_, 256>>>(Xc, n2, Hc);
    gemm(Hc, w1, p.U, BC_, DFF_, D_, false);
    gemm(Hc, w2, p.V2, BC_, DFF_, D_, false);
    swiglu_k<<<(BC_ * DFF_ + 255) / 256, 256>>>(p.U, p.V2, BC_ * DFF_);
    gemm(p.U, w3, Xc, BC_, D_, DFF_, true);
    scatter_k<<<BC_, 256>>>(Xc, p.CIDX, p.X);
}

extern "C" void kernel_launch(void* const* d_in, const int* in_sizes, int n_in,
                              void* d_out, int out_size) {
    const int*   ids       = (const int*)d_in[0];
    const float* embed_w   = (const float*)d_in[1];
    const float* pos_w     = (const float*)d_in[2];
    const float* qkv_w     = (const float*)d_in[3];
    const float* out_w     = (const float*)d_in[4];
    const float* norm1_w   = (const float*)d_in[5];
    const float* norm2_w   = (const float*)d_in[6];
    const float* ff_w1     = (const float*)d_in[7];
    const float* ff_w2     = (const float*)d_in[8];
    const float* ff_w3     = (const float*)d_in[9];
    const float* router_w  = (const float*)d_in[10];
    const float* lat_qkv_w = (const float*)d_in[11];
    const float* lat_out_w = (const float*)d_in[12];
    const float* lat_n1    = (const float*)d_in[13];
    const float* lat_n2    = (const float*)d_in[14];
    const float* lat_w1    = (const float*)d_in[15];
    const float* lat_w2    = (const float*)d_in[16];
    const float* lat_w3    = (const float*)d_in[17];
    const float* mem_keys  = (const float*)d_in[18];
    const float* mem_values= (const float*)d_in[19];
    const float* mem_qp    = (const float*)d_in[20];
    const float* mem_op    = (const float*)d_in[21];
    const float* gate_w1   = (const float*)d_in[22];
    const float* gate_b1   = (const float*)d_in[23];
    const float* gate_w2   = (const float*)d_in[24];
    const float* gate_b2   = (const float*)d_in[25];
    const float* final_nw  = (const float*)d_in[26];
    float* out = (float*)d_out;

    static bool attr_done = false;
    if (!attr_done) {
        cudaFuncSetAttribute(fattn_k, cudaFuncAttributeMaxDynamicSharedMemorySize, FA_SMEM);
        cudaFuncSetAttribute(fattn_mod_k, cudaFuncAttributeMaxDynamicSharedMemorySize, FAM_SMEM);
        cudaFuncSetAttribute(fattn_k, cudaFuncAttributePreferredSharedMemoryCarveout, 100);
        cudaFuncSetAttribute(fattn_mod_k, cudaFuncAttributePreferredSharedMemoryCarveout, 100);
        attr_done = true;
    }

    Ptrs p;
    cudaGetSymbolAddress((void**)&p.X, g_X);
    cudaGetSymbolAddress((void**)&p.Y, g_Y);
    cudaGetSymbolAddress((void**)&p.Hb, g_Hb);
    cudaGetSymbolAddress((void**)&p.QKV, g_QKV);
    cudaGetSymbolAddress((void**)&p.ATT, g_ATT);
    cudaGetSymbolAddress((void**)&p.U, g_U);
    cudaGetSymbolAddress((void**)&p.V2, g_V2);
    cudaGetSymbolAddress((void**)&p.SIM, g_SIM);
    cudaGetSymbolAddress((void**)&p.RETP, g_RETP);
    cudaGetSymbolAddress((void**)&p.RET, g_RET);
    cudaGetSymbolAddress((void**)&p.GI, g_GI);
    cudaGetSymbolAddress((void**)&p.H1, g_H1);
    cudaGetSymbolAddress((void**)&p.SC, g_SC);
    cudaGetSymbolAddress((void**)&p.CIDX, g_CIDX);

    embed_k<<<BT_, 256>>>(ids, embed_w, pos_w, p.X);

    for (int i = 0; i < L_; i++) {
        const float* qw = qkv_w + (size_t)i * QKVD_ * D_;
        const float* ow = out_w + (size_t)i * D_ * D_;
        const float* n1 = norm1_w + (size_t)i * D_;
        const float* n2 = norm2_w + (size_t)i * D_;
        const float* w1 = ff_w1 + (size_t)i * DFF_ * D_;
        const float* w2 = ff_w2 + (size_t)i * DFF_ * D_;
        const float* w3 = ff_w3 + (size_t)i * D_ * DFF_;
        if (i % 2 == 1)
            tblock_mod(p, qw, ow, n1, n2, w1, w2, w3, router_w + (size_t)i * D_);
        else
            tblock_full(p, qw, ow, n1, n2, w1, w2, w3, p.X);
    }

    for (int it = 0; it < NLAT_; it++)
        tblock_full(p, lat_qkv_w, lat_out_w, lat_n1, lat_n2, lat_w1, lat_w2, lat_w3, p.X);

    // kNN memory retrieval
    gemm(p.X, mem_qp, p.Hb, BT_, D_, D_, false);          // q
    gemm(p.Hb, mem_keys, p.SIM, BT_, NMEM_, D_, false);   // sim (unscaled)
    memtopk_k<<<BT_, 256>>>(p.SIM, mem_values, p.RETP);
    gemm(p.RETP, mem_op, p.RET, BT_, D_, D_, false);
    concat_k<<<BT_, 256>>>(p.X, p.RET, p.GI);
    gemm(p.GI, gate_w1, p.H1, BT_, D_ / 2, 2 * D_, false);
    gelu_bias_k<<<(BT_ * (D_ / 2) + 255) / 256, 256>>>(p.H1, gate_b1, BT_ * (D_ / 2));
    gate_k<<<BT_, 256>>>(p.H1, gate_w2, gate_b2, p.RET, p.X);

    // final norm + tied LM head
    rmsnorm_k<<<BT_, 256>>>(p.X, final_nw, p.Hb);
    gemm(p.Hb, embed_w, out, BT_, VOCAB_, D_, false);
}